// round 9
// baseline (speedup 1.0000x reference)
#include <cuda_runtime.h>
#include <cuda_bf16.h>
#include <math.h>
#include <stdint.h>

#define Cn   256
#define Hn   128
#define Wn   128
#define Bn   2
#define HWn  (Hn*Wn)        // 16384
#define NPIX (Bn*HWn)       // 32768
#define NCn  80
#define Kdcn 2304
#define WSZ  (Cn*Kdcn)      // 589824 words per layer
#define NCHUNK 72           // 2304/32
#define NELEM (Bn*Cn*HWn)   // 8388608
#define PKQ  (NELEM/4)      // 2097152

// per-stage: A 16KB ([128oc][32 words]), B 16KB ([128px][32 words]); XOR swz (ch^row&7)
#define A_OFF 0
#define B_OFF 16384
#define STG   32768

__device__ __forceinline__ uint32_t smem_to_u32(const void* p) {
    uint32_t a;
    asm("{ .reg .u64 t; cvta.to.shared.u64 t, %1; cvt.u32.u64 %0, t; }" : "=r"(a) : "l"(p));
    return a;
}
__device__ __forceinline__ void cpasync16(uint32_t dst, const void* src, uint32_t srcsz) {
    asm volatile("cp.async.cg.shared.global [%0], [%1], 16, %2;"
        :: "r"(dst), "l"(src), "r"(srcsz) : "memory");
}
__device__ __forceinline__ void cpcommit() {
    asm volatile("cp.async.commit_group;" ::: "memory");
}
__device__ __forceinline__ void ldsm4(uint32_t r[4], uint32_t addr) {
    asm volatile("ldmatrix.sync.aligned.m8n8.x4.shared.b16 {%0,%1,%2,%3}, [%4];"
        : "=r"(r[0]), "=r"(r[1]), "=r"(r[2]), "=r"(r[3]) : "r"(addr));
}
__device__ __forceinline__ void mma16816(float d[4], const uint32_t a[4],
                                         uint32_t b0, uint32_t b1) {
    asm volatile(
        "mma.sync.aligned.m16n8k16.row.col.f32.bf16.bf16.f32 "
        "{%0,%1,%2,%3}, {%4,%5,%6,%7}, {%8,%9}, {%0,%1,%2,%3};"
        : "+f"(d[0]), "+f"(d[1]), "+f"(d[2]), "+f"(d[3])
        : "r"(a[0]), "r"(a[1]), "r"(a[2]), "r"(a[3]), "r"(b0), "r"(b1));
}
__device__ __forceinline__ uint32_t prmt(uint32_t a, uint32_t b, uint32_t sel) {
    uint32_t d; asm("prmt.b32 %0,%1,%2,%3;" : "=r"(d) : "r"(a), "r"(b), "r"(sel));
    return d;
}
// packed word: low16 = bf16(v), high16 = bf16(v - bf16(v))
__device__ __forceinline__ uint32_t packpair(float v) {
    __nv_bfloat16 h = __float2bfloat16(v);
    float hf = __bfloat162float(h);
    __nv_bfloat16 l = __float2bfloat16(v - hf);
    uint16_t hb = *reinterpret_cast<uint16_t*>(&h);
    uint16_t lb = *reinterpret_cast<uint16_t*>(&l);
    return (uint32_t)hb | ((uint32_t)lb << 16);
}
__device__ __forceinline__ float unpack(uint32_t pk) {
    return __int_as_float(pk << 16) + __int_as_float(pk & 0xFFFF0000u);
}

// ---------------- scratch (channel-last packed activations) ----------------
__device__ uint32_t g_pkX [NELEM];
__device__ uint32_t g_pkA [NELEM];
__device__ uint32_t g_pkB [NELEM];
__device__ uint32_t g_clspk[NELEM];
__device__ uint32_t g_ptspk[NELEM];
__device__ float g_off [Bn*27*HWn];
__device__ float g_dcn [(size_t)Cn*NPIX];
__device__ __align__(16) uint32_t g_wpk[9*WSZ];

struct WPtrs { const float* w[9]; };

// ---------------- prep: pack x channel-last + all 9 weights (one launch) ----------------
__global__ void __launch_bounds__(256)
prep_kernel(const float* __restrict__ x, WPtrs wp,
            uint32_t* __restrict__ pkX, uint32_t* __restrict__ wpk)
{
    int gid = blockIdx.x * 256 + threadIdx.x;
    if (gid < PKQ) {
        int hw  = gid & (HWn - 1);
        int rem = gid >> 14;
        int cg  = rem & 63;
        int b   = rem >> 6;
        const float* src = x + ((size_t)(b*Cn + cg*4))*HWn + hw;
        uint4 o;
        o.x = packpair(__ldg(src));
        o.y = packpair(__ldg(src + HWn));
        o.z = packpair(__ldg(src + 2*HWn));
        o.w = packpair(__ldg(src + 3*HWn));
        *reinterpret_cast<uint4*>(pkX + ((size_t)(b*HWn + hw)*256 + cg*4)) = o;
    } else {
        int i = gid - PKQ;                 // < 9*WSZ
        int l = i / WSZ, r = i - l*WSZ;
        int oc = r / Kdcn, kp = r - oc*Kdcn;
        int tap = kp >> 8, ic = kp & 255;
        float v = wp.w[l][((size_t)oc*256 + ic)*9 + tap];
        wpk[i] = packpair(v);
    }
}

// =====================================================================
// Implicit-GEMM, interleaved hi/lo 2-pass MMA. D[128oc][128px] per CTA.
// MODE 0: conv3x3 pad1, 3-stage cp.async pipeline; bias+relu; out packed CL / fp32 NCHW
// MODE 1/2: dcn (mask / no mask), 2-stage, bilinear gather; out fp32 [oc][NPIX]
// =====================================================================
template<int MODE>
__global__ void __launch_bounds__(256, 2)
gemm_kernel(const uint32_t* __restrict__ pkfeat,
            const uint32_t* __restrict__ wpk,
            const float* __restrict__ bias, const float* __restrict__ off,
            float* __restrict__ outf, uint32_t* __restrict__ outp)
{
    constexpr int NSTG = (MODE == 0) ? 3 : 2;
    constexpr int METAOFF = NSTG * STG;

    extern __shared__ __align__(128) char smem[];
    const uint32_t sbase = smem_to_u32(smem);
    const int tid  = threadIdx.x;
    const int wid  = tid >> 5, lane = tid & 31;
    const int nblk = blockIdx.x;
    const int b = nblk >> 7, y = nblk & 127;
    const int ocbase = blockIdx.y * 128;

    const int m0 = (wid & 3) * 32;     // 4 m-warps x 32 oc
    const int n0 = (wid >> 2) * 64;    // 2 n-warps x 64 px

    const int l7  = lane & 7;
    const int aR  = l7 + ((lane >> 3) & 1) * 8;
    const int bpx = l7 + (lane >> 4) * 8;

    // ---- dcn metadata: bilinear weights + corner indices per (tap, px) ----
    if (MODE != 0) {
        for (int e = tid; e < 9*128; e += 256) {
            int tap = e >> 7, p = e & 127;
            int ky = tap / 3 - 1, kx = tap % 3 - 1;
            int hw = y * Wn + p;
            const float* offb = off + (size_t)b*27*HWn + hw;
            float offy = __ldg(offb + (size_t)(2*tap)*HWn);
            float offx = __ldg(offb + (size_t)(2*tap + 1)*HWn);
            float py = (float)(y + ky) + offy;
            float px = (float)(p + kx) + offx;
            float fy0 = floorf(py), fx0 = floorf(px);
            float ly = py - fy0, lx = px - fx0;
            bool vy0 = (fy0 >= 0.f)       && (fy0 <= 127.f);
            bool vy1 = (fy0 + 1.f >= 0.f) && (fy0 + 1.f <= 127.f);
            bool vx0 = (fx0 >= 0.f)       && (fx0 <= 127.f);
            bool vx1 = (fx0 + 1.f >= 0.f) && (fx0 + 1.f <= 127.f);
            float w00 = (1.f-ly)*(1.f-lx) * ((vy0 && vx0) ? 1.f : 0.f);
            float w01 = (1.f-ly)*lx       * ((vy0 && vx1) ? 1.f : 0.f);
            float w10 = ly*(1.f-lx)       * ((vy1 && vx0) ? 1.f : 0.f);
            float w11 = ly*lx             * ((vy1 && vx1) ? 1.f : 0.f);
            if (MODE == 1) {
                float m = __ldg(offb + (size_t)(18 + tap)*HWn);
                w00 *= m; w01 *= m; w10 *= m; w11 *= m;
            }
            int iy0 = min(max((int)fy0,     0), Hn-1);
            int iy1 = min(max((int)fy0 + 1, 0), Hn-1);
            int ix0 = min(max((int)fx0,     0), Wn-1);
            int ix1 = min(max((int)fx0 + 1, 0), Wn-1);
            char* mb = smem + METAOFF + e*32;
            *reinterpret_cast<float4*>(mb) = make_float4(w00, w01, w10, w11);
            *reinterpret_cast<int4*>(mb + 16) =
                make_int4(iy0*Wn + ix0, iy0*Wn + ix1, iy1*Wn + ix0, iy1*Wn + ix1);
        }
        __syncthreads();
    }

    float acc[16][4];
    #pragma unroll
    for (int i = 0; i < 16; i++)
        #pragma unroll
        for (int j = 0; j < 4; j++) acc[i][j] = 0.f;

    // ---------------- loader ----------------
    auto load_chunk = [&](int stg, int cc) {
        const uint32_t su = sbase + stg * STG;
        // A: 128 oc x 32 words via cp.async, XOR swizzle
        {
            int row = tid >> 1, seg = tid & 1;
            const uint32_t* src = wpk + (size_t)(ocbase + row) * Kdcn + cc * 32;
            uint32_t drow = su + A_OFF + row * 128;
            int sw = row & 7;
            #pragma unroll
            for (int i = 0; i < 4; i++) {
                int ch = seg*4 + i;
                cpasync16(drow + ((ch ^ sw) << 4), src + ch*4, 16);
            }
        }
        const int tap = cc >> 3;
        const int ic0 = (cc & 7) * 32;

        if (MODE == 0) {
            const int ky = tap / 3 - 1, kx = tap % 3 - 1;
            int p = tid >> 1, seg = tid & 1;
            int yy = y + ky, xx = p + kx;
            bool ok = (yy >= 0 && yy < Hn && xx >= 0 && xx < Wn);
            const uint32_t* src = pkfeat + ((size_t)(b*HWn + yy*Wn + xx)*256 + ic0);
            uint32_t srcsz = ok ? 16u : 0u;
            uint32_t drow = su + B_OFF + p * 128;
            int sw = p & 7;
            #pragma unroll
            for (int i = 0; i < 4; i++) {
                int ch = seg*4 + i;
                cpasync16(drow + ((ch ^ sw) << 4), src + ch*4, srcsz);
            }
            cpcommit();
        } else {
            cpcommit();
            int p = tid & 127, g = tid >> 7;
            const char* mb = smem + METAOFF + (tap*128 + p)*32;
            float4 wv = *reinterpret_cast<const float4*>(mb);
            int4  iv = *reinterpret_cast<const int4*>(mb + 16);
            const uint32_t* c0 = pkfeat + ((size_t)(b*HWn + iv.x)*256 + ic0 + g*16);
            const uint32_t* c1 = pkfeat + ((size_t)(b*HWn + iv.y)*256 + ic0 + g*16);
            const uint32_t* c2 = pkfeat + ((size_t)(b*HWn + iv.z)*256 + ic0 + g*16);
            const uint32_t* c3 = pkfeat + ((size_t)(b*HWn + iv.w)*256 + ic0 + g*16);
            char* drow = smem + stg*STG + B_OFF + p * 128;
            int sw = p & 7;
            #pragma unroll
            for (int q = 0; q < 4; q++) {
                uint4 u0 = *reinterpret_cast<const uint4*>(c0 + q*4);
                uint4 u1 = *reinterpret_cast<const uint4*>(c1 + q*4);
                uint4 u2 = *reinterpret_cast<const uint4*>(c2 + q*4);
                uint4 u3 = *reinterpret_cast<const uint4*>(c3 + q*4);
                uint4 o;
                o.x = packpair(wv.x*unpack(u0.x) + wv.y*unpack(u1.x) + wv.z*unpack(u2.x) + wv.w*unpack(u3.x));
                o.y = packpair(wv.x*unpack(u0.y) + wv.y*unpack(u1.y) + wv.z*unpack(u2.y) + wv.w*unpack(u3.y));
                o.z = packpair(wv.x*unpack(u0.z) + wv.y*unpack(u1.z) + wv.z*unpack(u2.z) + wv.w*unpack(u3.z));
                o.w = packpair(wv.x*unpack(u0.w) + wv.y*unpack(u1.w) + wv.z*unpack(u2.w) + wv.w*unpack(u3.w));
                int ch = g*4 + q;
                *reinterpret_cast<uint4*>(drow + ((ch ^ sw) << 4)) = o;
            }
        }
    };

    // ---------------- compute: 2-pass interleaved hi/lo ----------------
    auto compute = [&](int stg) {
        const uint32_t Ab = sbase + stg*STG + A_OFF;
        const uint32_t Bb = sbase + stg*STG + B_OFF;
        #pragma unroll
        for (int s2 = 0; s2 < 4; s2++) {
            uint32_t cxA = (uint32_t)(((s2*2 + (lane >> 4)) ^ l7) << 4);
            uint32_t cxB = (uint32_t)(((s2*2 + ((lane >> 3) & 1)) ^ l7) << 4);
            uint32_t a0[4], a1[4], s0[4], s1[4];
            ldsm4(a0, Ab + (uint32_t)((m0 + aR)*128)      + cxA);
            ldsm4(a1, Ab + (uint32_t)((m0 + 16 + aR)*128) + cxA);
            #pragma unroll
            for (int j = 0; j < 4; j++) {
                s0[j] = prmt(a0[j], a0[j], 0x1032);
                s1[j] = prmt(a1[j], a1[j], 0x1032);
            }
            #pragma unroll
            for (int nb = 0; nb < 4; nb++) {
                uint32_t bb[4];
                ldsm4(bb, Bb + (uint32_t)((n0 + nb*16 + bpx)*128) + cxB);
                mma16816(acc[nb*2 + 0],     a0, bb[0], bb[1]);
                mma16816(acc[nb*2 + 1],     a0, bb[2], bb[3]);
                mma16816(acc[8 + nb*2 + 0], a1, bb[0], bb[1]);
                mma16816(acc[8 + nb*2 + 1], a1, bb[2], bb[3]);
                mma16816(acc[nb*2 + 0],     s0, bb[0], bb[1]);
                mma16816(acc[nb*2 + 1],     s0, bb[2], bb[3]);
                mma16816(acc[8 + nb*2 + 0], s1, bb[0], bb[1]);
                mma16816(acc[8 + nb*2 + 1], s1, bb[2], bb[3]);
            }
        }
    };

    // ---------------- main loop ----------------
    if (MODE == 0) {
        load_chunk(0, 0);
        load_chunk(1, 1);
        for (int c = 0; c < NCHUNK; c++) {
            asm volatile("cp.async.wait_group 1;" ::: "memory");
            __syncthreads();
            if (c + 2 < NCHUNK) load_chunk((c + 2) % 3, c + 2);
            compute(c % 3);
        }
    } else {
        load_chunk(0, 0);
        asm volatile("cp.async.wait_group 0;" ::: "memory");
        __syncthreads();
        for (int c = 0; c < NCHUNK; c++) {
            int cur = c & 1;
            if (c + 1 < NCHUNK) load_chunk(cur ^ 1, c + 1);
            compute(cur);
            asm volatile("cp.async.wait_group 0;" ::: "memory");
            __syncthreads();
        }
    }

    // ---------------- epilogue ----------------
    const int r  = lane >> 2;
    const int c2 = (lane & 3) * 2;

    if (MODE == 0) {
        // stage packed D into smem [px][oc swizzled], then coalesced STG
        __syncthreads();
        uint32_t* st = reinterpret_cast<uint32_t*>(smem);
        #pragma unroll
        for (int mt = 0; mt < 2; mt++) {
            #pragma unroll
            for (int rr = 0; rr < 2; rr++) {
                int oc_l = m0 + mt*16 + r + rr*8;
                float bv = bias ? __ldg(&bias[ocbase + oc_l]) : 0.f;
                #pragma unroll
                for (int nt = 0; nt < 8; nt++) {
                    float* d = acc[mt*8 + nt];
                    int x0 = n0 + nt*8 + c2;
                    float v0 = fmaxf(d[rr*2]   + bv, 0.f);
                    float v1 = fmaxf(d[rr*2+1] + bv, 0.f);
                    st[x0*128     + (oc_l ^ ((x0     & 7) << 2))] = packpair(v0);
                    st[(x0+1)*128 + (oc_l ^ (((x0+1) & 7) << 2))] = packpair(v1);
                    if (outf) {
                        float2 fv = { v0, v1 };
                        *reinterpret_cast<float2*>(outf +
                            ((size_t)(b*Cn + ocbase + oc_l))*HWn + y*Wn + x0) = fv;
                    }
                }
            }
        }
        __syncthreads();
        if (outp) {
            int p = tid >> 1, half = tid & 1;
            uint32_t* dst = outp + ((size_t)(b*HWn + y*Wn + p)*256 + ocbase + half*64);
            int sw = (p & 7) << 2;
            #pragma unroll
            for (int j4 = 0; j4 < 16; j4++) {
                int w = half*64 + j4*4;
                uint4 v = *reinterpret_cast<const uint4*>(st + p*128 + (w ^ sw));
                *reinterpret_cast<uint4*>(dst + j4*4) = v;
            }
        }
    } else {
        #pragma unroll
        for (int mt = 0; mt < 2; mt++) {
            #pragma unroll
            for (int rr = 0; rr < 2; rr++) {
                int oc = ocbase + m0 + mt*16 + r + rr*8;
                #pragma unroll
                for (int nt = 0; nt < 8; nt++) {
                    float* d = acc[mt*8 + nt];
                    int x = n0 + nt*8 + c2;
                    float2 fv = { fmaxf(d[rr*2], 0.f), fmaxf(d[rr*2+1], 0.f) };
                    *reinterpret_cast<float2*>(outf +
                        (size_t)oc*NPIX + (size_t)b*HWn + y*Wn + x) = fv;
                }
            }
        }
    }
}

// ---------------- small kernels ----------------
// 1x1 conv 27ch from packed CL input (contiguous 1KB per pixel)
__global__ void __launch_bounds__(256)
conv1x1_27_kernel(const uint32_t* __restrict__ pk, const float* __restrict__ wgt,
                  const float* __restrict__ bias, float* __restrict__ out)
{
    __shared__ float ws[Cn*27];
    for (int idx = threadIdx.x; idx < Cn*27; idx += 256) {
        int o = idx >> 8, ic = idx & 255;
        ws[ic*27 + o] = wgt[(size_t)o*Cn + ic];
    }
    __syncthreads();
    int p  = blockIdx.x * 256 + threadIdx.x;
    int b  = p >> 14;
    int hw = p & (HWn - 1);
    float acc[27];
    #pragma unroll
    for (int o = 0; o < 27; o++) acc[o] = 0.f;
    const uint4* ip = reinterpret_cast<const uint4*>(pk + (size_t)p*256);
    for (int ic4 = 0; ic4 < 64; ic4++) {
        uint4 w = __ldg(ip + ic4);
        float v0 = unpack(w.x), v1 = unpack(w.y), v2 = unpack(w.z), v3 = unpack(w.w);
        const float* w0 = &ws[(ic4*4)*27];
        #pragma unroll
        for (int o = 0; o < 27; o++)
            acc[o] += v0*w0[o] + v1*w0[27+o] + v2*w0[54+o] + v3*w0[81+o];
    }
    #pragma unroll
    for (int o = 0; o < 27; o++)
        out[((size_t)(b*27) + o)*HWn + hw] = acc[o] + bias[o];
}

__global__ void __launch_bounds__(256)
conv1x1_cls_kernel(const float* __restrict__ in, const float* __restrict__ wgt,
                   const float* __restrict__ bias, float* __restrict__ out)
{
    __shared__ float ws[Cn*16];
    int g = blockIdx.y;
    for (int idx = threadIdx.x; idx < Cn*16; idx += 256) {
        int j = idx >> 8, ic = idx & 255;
        ws[ic*16 + j] = wgt[(size_t)(g*16 + j)*Cn + ic];
    }
    __syncthreads();
    int p  = blockIdx.x * 256 + threadIdx.x;
    int b  = p >> 14;
    int hw = p & (HWn - 1);
    float acc[16];
    #pragma unroll
    for (int j = 0; j < 16; j++) acc[j] = 0.f;
    for (int ic = 0; ic < Cn; ic++) {
        float v = __ldg(&in[(size_t)ic*NPIX + p]);
        #pragma unroll
        for (int j = 0; j < 16; j++) acc[j] += v * ws[ic*16 + j];
    }
    #pragma unroll
    for (int j = 0; j < 16; j++) {
        int oc = g*16 + j;
        out[((size_t)(b*NCn) + oc)*HWn + hw] = acc[j] + bias[oc];
    }
}

__global__ void __launch_bounds__(256)
ref_fused_kernel(const float* __restrict__ in, const float* __restrict__ wgt,
                 const float* __restrict__ bias, const float* __restrict__ off,
                 float* __restrict__ dout)
{
    __shared__ float ws[Cn*18];
    for (int idx = threadIdx.x; idx < Cn*18; idx += 256) {
        int o = idx >> 8, ic = idx & 255;
        ws[ic*18 + o] = wgt[(size_t)o*Cn + ic];
    }
    __syncthreads();
    int p  = blockIdx.x * 256 + threadIdx.x;
    int b  = p >> 14;
    int hw = p & (HWn - 1);
    float acc[18];
    #pragma unroll
    for (int o = 0; o < 18; o++) acc[o] = 0.f;
    for (int ic = 0; ic < Cn; ic++) {
        float v = __ldg(&in[(size_t)ic*NPIX + p]);
        #pragma unroll
        for (int o = 0; o < 18; o++) acc[o] += v * ws[ic*18 + o];
    }
    float refine[18];
    #pragma unroll
    for (int o = 0; o < 18; o++)
        refine[o] = acc[o] + bias[o] + off[((size_t)(b*27) + o)*HWn + hw];
    float m0 = 0.f, m1 = 0.f;
    #pragma unroll
    for (int q = 0; q < 9; q++) { m0 += refine[2*q]; m1 += refine[2*q + 1]; }
    m0 *= (1.f/9.f); m1 *= (1.f/9.f);
    float wh0 = 0.f, wh1 = 0.f;
    #pragma unroll
    for (int q = 0; q < 9; q++) {
        wh0 = fmaxf(wh0, fabsf(refine[2*q]     + m0));
        wh1 = fmaxf(wh1, fabsf(refine[2*q + 1] + m1));
    }
    const size_t OUT_WH  = (size_t)Bn*NCn*HWn;
    const size_t OUT_REG = OUT_WH + (size_t)Bn*2*HWn;
    dout[OUT_WH  + ((size_t)(b*2) + 0)*HWn + hw] = wh0;
    dout[OUT_WH  + ((size_t)(b*2) + 1)*HWn + hw] = wh1;
    dout[OUT_REG + ((size_t)(b*2) + 0)*HWn + hw] = m0;
    dout[OUT_REG + ((size_t)(b*2) + 1)*HWn + hw] = m1;
}

// =====================================================================
extern "C" void kernel_launch(void* const* d_in, const int* in_sizes, int n_in,
                              void* d_out, int out_size)
{
    const float* x = (const float*)d_in[0];
    WPtrs wp;
    wp.w[0] = (const float*)d_in[1];   // cls_w0
    wp.w[1] = (const float*)d_in[5];   // cls_w1
    wp.w[2] = (const float*)d_in[9];   // cls_w2
    wp.w[3] = (const float*)d_in[3];   // reg_w0
    wp.w[4] = (const float*)d_in[7];   // reg_w1
    wp.w[5] = (const float*)d_in[11];  // reg_w2
    wp.w[6] = (const float*)d_in[13];  // init_conv_w
    wp.w[7] = (const float*)d_in[17];  // dcn_cls_w
    wp.w[8] = (const float*)d_in[20];  // dcn_ref_w
    const float* cls_b0      = (const float*)d_in[2];
    const float* cls_b1      = (const float*)d_in[6];
    const float* cls_b2      = (const float*)d_in[10];
    const float* reg_b0      = (const float*)d_in[4];
    const float* reg_b1      = (const float*)d_in[8];
    const float* reg_b2      = (const float*)d_in[12];
    const float* init_conv_b = (const float*)d_in[14];
    const float* init_out_w  = (const float*)d_in[15];
    const float* init_out_b  = (const float*)d_in[16];
    const float* cls_out_w   = (const float*)d_in[18];
    const float* cls_out_b   = (const float*)d_in[19];
    const float* ref_out_w   = (const float*)d_in[21];
    const float* ref_out_b   = (const float*)d_in[22];
    float* out = (float*)d_out;

    uint32_t *pkX, *pkA, *pkB, *clspk, *ptspk, *wpk;
    float *off, *dcn;
    cudaGetSymbolAddress((void**)&pkX,   g_pkX);
    cudaGetSymbolAddress((void**)&pkA,   g_pkA);
    cudaGetSymbolAddress((void**)&pkB,   g_pkB);
    cudaGetSymbolAddress((void**)&clspk, g_clspk);
    cudaGetSymbolAddress((void**)&ptspk, g_ptspk);
    cudaGetSymbolAddress((void**)&wpk,   g_wpk);
    cudaGetSymbolAddress((void**)&off,   g_off);
    cudaGetSymbolAddress((void**)&dcn,   g_dcn);

    const int SMEM_CONV = 3*STG;                 // 98304
    const int SMEM_DCN  = 2*STG + 9*128*32;      // 102400
    cudaFuncSetAttribute(gemm_kernel<0>, cudaFuncAttributeMaxDynamicSharedMemorySize, SMEM_CONV);
    cudaFuncSetAttribute(gemm_kernel<1>, cudaFuncAttributeMaxDynamicSharedMemorySize, SMEM_DCN);
    cudaFuncSetAttribute(gemm_kernel<2>, cudaFuncAttributeMaxDynamicSharedMemorySize, SMEM_DCN);

    dim3 gg(256, 2);
    #define GCONV(in_, l, bias_, of_, op_) \
        gemm_kernel<0><<<gg, 256, SMEM_CONV>>>(in_, wpk + (size_t)(l)*WSZ, bias_, nullptr, of_, op_)
    #define GDCN(md, in_, l, of_) \
        gemm_kernel<md><<<gg, 256, SMEM_DCN>>>(in_, wpk + (size_t)(l)*WSZ, nullptr, off, of_, nullptr)

    prep_kernel<<<(PKQ + 9*WSZ)/256, 256>>>(x, wp, pkX, wpk);

    // cls tower (packed CL chain)
    GCONV(pkX, 0, cls_b0, nullptr, pkA);
    GCONV(pkA, 1, cls_b1, nullptr, pkB);
    GCONV(pkB, 2, cls_b2, nullptr, clspk);
    // reg tower
    GCONV(pkX, 3, reg_b0, nullptr, pkA);
    GCONV(pkA, 4, reg_b1, nullptr, pkB);
    GCONV(pkB, 5, reg_b2, nullptr, ptspk);
    // init branch: conv3x3 -> packed CL -> 1x1 (reads packed)
    GCONV(ptspk, 6, init_conv_b, nullptr, pkA);
    conv1x1_27_kernel<<<128, 256>>>(pkA, init_out_w, init_out_b, off);

    // cls dcn (mask) -> cls head
    GDCN(1, clspk, 7, dcn);
    conv1x1_cls_kernel<<<dim3(128, 5), 256>>>(dcn, cls_out_w, cls_out_b, out);

    // ref dcn (no mask) -> fused refine/wh/reg
    GDCN(2, ptspk, 8, dcn);
    ref_fused_kernel<<<128, 256>>>(dcn, ref_out_w, ref_out_b, off, out);
}

// round 10
// speedup vs baseline: 1.2108x; 1.2108x over previous
#include <cuda_runtime.h>
#include <cuda_bf16.h>
#include <math.h>
#include <stdint.h>

#define Cn   256
#define Hn   128
#define Wn   128
#define Bn   2
#define HWn  (Hn*Wn)        // 16384
#define NPIX (Bn*HWn)       // 32768
#define NCn  80
#define Kdcn 2304
#define WSZ  (Cn*Kdcn)      // 589824 words per layer
#define NCHUNK 72
#define NELEM (Bn*Cn*HWn)   // 8388608
#define PKQ  (NELEM/4)

// conv per-stage: A 16KB ([128oc][32w]) + B 16KB ([128px][32w]); XOR swz (ch^row&7)
#define CA_OFF 0
#define CB_OFF 16384
#define CSTG   32768
#define CONV_SMEM (2*CSTG)            // 65536

// dcn per-stage: A 32KB ([256oc][32w]) + B 8KB ([64px][32w])
#define DA_OFF 0
#define DB_OFF 32768
#define DSTG   40960
#define DMETA  (2*DSTG)               // 81920
#define DCN_SMEM (DMETA + 9*64*32)    // 100352

__device__ __forceinline__ uint32_t smem_to_u32(const void* p) {
    uint32_t a;
    asm("{ .reg .u64 t; cvta.to.shared.u64 t, %1; cvt.u32.u64 %0, t; }" : "=r"(a) : "l"(p));
    return a;
}
__device__ __forceinline__ void cpasync16(uint32_t dst, const void* src, uint32_t srcsz) {
    asm volatile("cp.async.cg.shared.global [%0], [%1], 16, %2;"
        :: "r"(dst), "l"(src), "r"(srcsz) : "memory");
}
__device__ __forceinline__ void cpcommit() {
    asm volatile("cp.async.commit_group;" ::: "memory");
}
__device__ __forceinline__ void cpwait0() {
    asm volatile("cp.async.wait_group 0;" ::: "memory");
}
__device__ __forceinline__ void ldsm4(uint32_t r[4], uint32_t addr) {
    asm volatile("ldmatrix.sync.aligned.m8n8.x4.shared.b16 {%0,%1,%2,%3}, [%4];"
        : "=r"(r[0]), "=r"(r[1]), "=r"(r[2]), "=r"(r[3]) : "r"(addr));
}
__device__ __forceinline__ void mma16816(float d[4], const uint32_t a[4],
                                         uint32_t b0, uint32_t b1) {
    asm volatile(
        "mma.sync.aligned.m16n8k16.row.col.f32.bf16.bf16.f32 "
        "{%0,%1,%2,%3}, {%4,%5,%6,%7}, {%8,%9}, {%0,%1,%2,%3};"
        : "+f"(d[0]), "+f"(d[1]), "+f"(d[2]), "+f"(d[3])
        : "r"(a[0]), "r"(a[1]), "r"(a[2]), "r"(a[3]), "r"(b0), "r"(b1));
}
__device__ __forceinline__ uint32_t prmt(uint32_t a, uint32_t b, uint32_t sel) {
    uint32_t d; asm("prmt.b32 %0,%1,%2,%3;" : "=r"(d) : "r"(a), "r"(b), "r"(sel));
    return d;
}
// packed word: low16 = bf16(v), high16 = bf16(v - bf16(v))
__device__ __forceinline__ uint32_t packpair(float v) {
    __nv_bfloat16 h = __float2bfloat16(v);
    float hf = __bfloat162float(h);
    __nv_bfloat16 l = __float2bfloat16(v - hf);
    uint16_t hb = *reinterpret_cast<uint16_t*>(&h);
    uint16_t lb = *reinterpret_cast<uint16_t*>(&l);
    return (uint32_t)hb | ((uint32_t)lb << 16);
}
__device__ __forceinline__ float unpack(uint32_t pk) {
    return __int_as_float(pk << 16) + __int_as_float(pk & 0xFFFF0000u);
}

// ---------------- scratch (channel-last packed activations) ----------------
__device__ uint32_t g_pkX [NELEM];
__device__ uint32_t g_cA  [NELEM];
__device__ uint32_t g_rA  [NELEM];
__device__ uint32_t g_cB  [NELEM];
__device__ uint32_t g_rB  [NELEM];
__device__ uint32_t g_clspk[NELEM];
__device__ uint32_t g_ptspk[NELEM];
__device__ float g_off [Bn*27*HWn];
__device__ float g_dcn0[(size_t)Cn*NPIX];
__device__ float g_dcn1[(size_t)Cn*NPIX];
__device__ __align__(16) uint32_t g_wpk[9*WSZ];

struct WPtrs { const float* w[9]; };

// ---------------- prep: pack x channel-last + split all 9 weights ----------------
__global__ void __launch_bounds__(256)
prep_kernel(const float* __restrict__ x, WPtrs wp,
            uint32_t* __restrict__ pkX, uint32_t* __restrict__ wpk)
{
    int gid = blockIdx.x * 256 + threadIdx.x;
    if (gid < PKQ) {
        int hw  = gid & (HWn - 1);
        int rem = gid >> 14;
        int cg  = rem & 63;
        int b   = rem >> 6;
        const float* src = x + ((size_t)(b*Cn + cg*4))*HWn + hw;
        uint4 o;
        o.x = packpair(__ldg(src));
        o.y = packpair(__ldg(src + HWn));
        o.z = packpair(__ldg(src + 2*HWn));
        o.w = packpair(__ldg(src + 3*HWn));
        *reinterpret_cast<uint4*>(pkX + ((size_t)(b*HWn + hw)*256 + cg*4)) = o;
    } else {
        int i = gid - PKQ;
        int l = i / WSZ, r = i - l*WSZ;
        int oc = r / Kdcn, kp = r - oc*Kdcn;
        int tap = kp >> 8, ic = kp & 255;
        float v = wp.w[l][((size_t)oc*256 + ic)*9 + tap];
        wpk[i] = packpair(v);
    }
}

// =====================================================================
// Dual-job conv3x3: blockIdx.z selects job. D[128oc][128px] per CTA.
// 256 threads, 2 CTA/SM, 2-stage cp.async, interleaved hi/lo 2-pass MMA.
// out: packed CL only.
// =====================================================================
struct ConvJob {
    const uint32_t* in;
    const uint32_t* w;
    const float*    bias;
    uint32_t*       outp;
};

__global__ void __launch_bounds__(256, 2)
conv_kernel(ConvJob j0, ConvJob j1)
{
    extern __shared__ __align__(128) char smem[];
    const ConvJob J = blockIdx.z ? j1 : j0;
    const uint32_t sbase = smem_to_u32(smem);
    const int tid  = threadIdx.x;
    const int wid  = tid >> 5, lane = tid & 31;
    const int nblk = blockIdx.x;
    const int b = nblk >> 7, y = nblk & 127;
    const int ocbase = blockIdx.y * 128;

    const int m0 = (wid & 3) * 32;
    const int n0 = (wid >> 2) * 64;
    const int l7  = lane & 7;
    const int aR  = l7 + ((lane >> 3) & 1) * 8;
    const int bpx = l7 + (lane >> 4) * 8;

    float acc[16][4];
    #pragma unroll
    for (int i = 0; i < 16; i++)
        #pragma unroll
        for (int j = 0; j < 4; j++) acc[i][j] = 0.f;

    auto load_chunk = [&](int stg, int cc) {
        const uint32_t su = sbase + stg * CSTG;
        {   // A: 128 oc x 32 words
            int row = tid >> 1, seg = tid & 1;
            const uint32_t* src = J.w + (size_t)(ocbase + row) * Kdcn + cc * 32;
            uint32_t drow = su + CA_OFF + row * 128;
            int sw = row & 7;
            #pragma unroll
            for (int i = 0; i < 4; i++) {
                int ch = seg*4 + i;
                cpasync16(drow + ((ch ^ sw) << 4), src + ch*4, 16);
            }
        }
        const int tap = cc >> 3;
        const int ic0 = (cc & 7) * 32;
        const int ky = tap / 3 - 1, kx = tap % 3 - 1;
        int p = tid >> 1, seg = tid & 1;
        int yy = y + ky, xx = p + kx;
        bool ok = (yy >= 0 && yy < Hn && xx >= 0 && xx < Wn);
        const uint32_t* src = J.in + ((size_t)(b*HWn + yy*Wn + xx)*256 + ic0);
        uint32_t srcsz = ok ? 16u : 0u;
        uint32_t drow = su + CB_OFF + p * 128;
        int sw = p & 7;
        #pragma unroll
        for (int i = 0; i < 4; i++) {
            int ch = seg*4 + i;
            cpasync16(drow + ((ch ^ sw) << 4), src + ch*4, srcsz);
        }
        cpcommit();
    };

    auto compute = [&](int stg) {
        const uint32_t Ab = sbase + stg*CSTG + CA_OFF;
        const uint32_t Bb = sbase + stg*CSTG + CB_OFF;
        #pragma unroll
        for (int s2 = 0; s2 < 4; s2++) {
            uint32_t cxA = (uint32_t)(((s2*2 + (lane >> 4)) ^ l7) << 4);
            uint32_t cxB = (uint32_t)(((s2*2 + ((lane >> 3) & 1)) ^ l7) << 4);
            uint32_t a0[4], a1[4], s0[4], s1[4];
            ldsm4(a0, Ab + (uint32_t)((m0 + aR)*128)      + cxA);
            ldsm4(a1, Ab + (uint32_t)((m0 + 16 + aR)*128) + cxA);
            #pragma unroll
            for (int j = 0; j < 4; j++) {
                s0[j] = prmt(a0[j], a0[j], 0x1032);
                s1[j] = prmt(a1[j], a1[j], 0x1032);
            }
            #pragma unroll
            for (int nb = 0; nb < 4; nb++) {
                uint32_t bb[4];
                ldsm4(bb, Bb + (uint32_t)((n0 + nb*16 + bpx)*128) + cxB);
                mma16816(acc[nb*2 + 0],     a0, bb[0], bb[1]);
                mma16816(acc[nb*2 + 1],     a0, bb[2], bb[3]);
                mma16816(acc[8 + nb*2 + 0], a1, bb[0], bb[1]);
                mma16816(acc[8 + nb*2 + 1], a1, bb[2], bb[3]);
                mma16816(acc[nb*2 + 0],     s0, bb[0], bb[1]);
                mma16816(acc[nb*2 + 1],     s0, bb[2], bb[3]);
                mma16816(acc[8 + nb*2 + 0], s1, bb[0], bb[1]);
                mma16816(acc[8 + nb*2 + 1], s1, bb[2], bb[3]);
            }
        }
    };

    load_chunk(0, 0);
    cpwait0();
    __syncthreads();
    for (int c = 0; c < NCHUNK; c++) {
        int cur = c & 1;
        if (c + 1 < NCHUNK) load_chunk(cur ^ 1, c + 1);
        compute(cur);
        cpwait0();
        __syncthreads();
    }

    // epilogue: stage packed D into smem [px][oc swz], coalesced 16B stores
    const int r  = lane >> 2;
    const int c2 = (lane & 3) * 2;
    __syncthreads();
    uint32_t* st = reinterpret_cast<uint32_t*>(smem);
    #pragma unroll
    for (int mt = 0; mt < 2; mt++) {
        #pragma unroll
        for (int rr = 0; rr < 2; rr++) {
            int oc_l = m0 + mt*16 + r + rr*8;
            float bv = __ldg(&J.bias[ocbase + oc_l]);
            #pragma unroll
            for (int nt = 0; nt < 8; nt++) {
                float* d = acc[mt*8 + nt];
                int x0 = n0 + nt*8 + c2;
                float v0 = fmaxf(d[rr*2]   + bv, 0.f);
                float v1 = fmaxf(d[rr*2+1] + bv, 0.f);
                st[x0*128     + (oc_l ^ ((x0     & 7) << 2))] = packpair(v0);
                st[(x0+1)*128 + (oc_l ^ (((x0+1) & 7) << 2))] = packpair(v1);
            }
        }
    }
    __syncthreads();
    {
        int p = tid >> 1, half = tid & 1;
        uint32_t* dst = J.outp + ((size_t)(b*HWn + y*Wn + p)*256 + ocbase + half*64);
        int sw = (p & 7) << 2;
        #pragma unroll
        for (int j4 = 0; j4 < 16; j4++) {
            int w = half*64 + j4*4;
            uint4 v = *reinterpret_cast<const uint4*>(st + p*128 + (w ^ sw));
            *reinterpret_cast<uint4*>(dst + j4*4) = v;
        }
    }
}

// =====================================================================
// Dual-job deformable conv: blockIdx.z selects (feat, w, mask, out).
// D[256oc][64px] per CTA — gather each pixel ONCE. 256 thr, 2 CTA/SM, grid (512,1,2).
// warp tile: 64oc x 32px (4 m-warps x 2 n-warps).
// =====================================================================
__global__ void __launch_bounds__(256, 2)
dcn_kernel(const uint32_t* __restrict__ f0, const uint32_t* __restrict__ f1,
           const uint32_t* __restrict__ w0, const uint32_t* __restrict__ w1,
           const float* __restrict__ off,
           float* __restrict__ o0, float* __restrict__ o1)
{
    extern __shared__ __align__(128) char smem[];
    const int z = blockIdx.z;
    const uint32_t* feat = z ? f1 : f0;
    const uint32_t* wpk  = z ? w1 : w0;
    float* outf          = z ? o1 : o0;
    const bool use_mask  = (z == 0);

    const uint32_t sbase = smem_to_u32(smem);
    const int tid  = threadIdx.x;
    const int wid  = tid >> 5, lane = tid & 31;
    const int pxb  = blockIdx.x * 64;

    const int m0 = (wid & 3) * 64;     // 4 m-warps x 64 oc
    const int n0 = (wid >> 2) * 32;    // 2 n-warps x 32 px
    const int l7  = lane & 7;
    const int aR  = l7 + ((lane >> 3) & 1) * 8;
    const int bpx = l7 + (lane >> 4) * 8;

    // ---- meta: bilinear weights + corner indices per (tap, px) ----
    for (int e = tid; e < 9*64; e += 256) {
        int tap = e >> 6, p = e & 63;
        int pg = pxb + p;
        int b  = pg >> 14;
        int hw = pg & (HWn - 1);
        int y  = hw >> 7, x = hw & 127;
        int ky = tap / 3 - 1, kx = tap % 3 - 1;
        const float* offb = off + (size_t)b*27*HWn + hw;
        float offy = __ldg(offb + (size_t)(2*tap)*HWn);
        float offx = __ldg(offb + (size_t)(2*tap + 1)*HWn);
        float py = (float)(y + ky) + offy;
        float px = (float)(x + kx) + offx;
        float fy0 = floorf(py), fx0 = floorf(px);
        float ly = py - fy0, lx = px - fx0;
        bool vy0 = (fy0 >= 0.f)       && (fy0 <= 127.f);
        bool vy1 = (fy0 + 1.f >= 0.f) && (fy0 + 1.f <= 127.f);
        bool vx0 = (fx0 >= 0.f)       && (fx0 <= 127.f);
        bool vx1 = (fx0 + 1.f >= 0.f) && (fx0 + 1.f <= 127.f);
        float w00 = (1.f-ly)*(1.f-lx) * ((vy0 && vx0) ? 1.f : 0.f);
        float w01 = (1.f-ly)*lx       * ((vy0 && vx1) ? 1.f : 0.f);
        float w10 = ly*(1.f-lx)       * ((vy1 && vx0) ? 1.f : 0.f);
        float w11 = ly*lx             * ((vy1 && vx1) ? 1.f : 0.f);
        if (use_mask) {
            float m = __ldg(offb + (size_t)(18 + tap)*HWn);
            w00 *= m; w01 *= m; w10 *= m; w11 *= m;
        }
        int iy0 = min(max((int)fy0,     0), Hn-1);
        int iy1 = min(max((int)fy0 + 1, 0), Hn-1);
        int ix0 = min(max((int)fx0,     0), Wn-1);
        int ix1 = min(max((int)fx0 + 1, 0), Wn-1);
        char* mb = smem + DMETA + e*32;
        *reinterpret_cast<float4*>(mb) = make_float4(w00, w01, w10, w11);
        // store global pixel base offsets (pre-multiplied by 256 words happens below)
        *reinterpret_cast<int4*>(mb + 16) =
            make_int4(b*HWn + iy0*Wn + ix0, b*HWn + iy0*Wn + ix1,
                      b*HWn + iy1*Wn + ix0, b*HWn + iy1*Wn + ix1);
    }
    __syncthreads();

    float acc[16][4];
    #pragma unroll
    for (int i = 0; i < 16; i++)
        #pragma unroll
        for (int j = 0; j < 4; j++) acc[i][j] = 0.f;

    auto load_chunk = [&](int stg, int cc) {
        const uint32_t su = sbase + stg * DSTG;
        {   // A: 256 oc x 32 words, one row per thread, 8 cp.async
            const uint32_t* src = wpk + (size_t)tid * Kdcn + cc * 32;
            uint32_t drow = su + DA_OFF + tid * 128;
            int sw = tid & 7;
            #pragma unroll
            for (int ch = 0; ch < 8; ch++)
                cpasync16(drow + ((ch ^ sw) << 4), src + ch*4, 16);
        }
        cpcommit();
        const int tap = cc >> 3;
        const int ic0 = (cc & 7) * 32;
        // B gather: px = tid&63, grp = tid>>6 (8 words each)
        int p = tid & 63, g = tid >> 6;
        const char* mb = smem + DMETA + (tap*64 + p)*32;
        float4 wv = *reinterpret_cast<const float4*>(mb);
        int4  iv = *reinterpret_cast<const int4*>(mb + 16);
        const uint32_t* c0 = feat + ((size_t)iv.x*256 + ic0 + g*8);
        const uint32_t* c1 = feat + ((size_t)iv.y*256 + ic0 + g*8);
        const uint32_t* c2 = feat + ((size_t)iv.z*256 + ic0 + g*8);
        const uint32_t* c3 = feat + ((size_t)iv.w*256 + ic0 + g*8);
        char* drow = smem + stg*DSTG + DB_OFF + p * 128;
        int sw = p & 7;
        #pragma unroll
        for (int q = 0; q < 2; q++) {
            uint4 u0 = *reinterpret_cast<const uint4*>(c0 + q*4);
            uint4 u1 = *reinterpret_cast<const uint4*>(c1 + q*4);
            uint4 u2 = *reinterpret_cast<const uint4*>(c2 + q*4);
            uint4 u3 = *reinterpret_cast<const uint4*>(c3 + q*4);
            uint4 o;
            o.x = packpair(wv.x*unpack(u0.x) + wv.y*unpack(u1.x) + wv.z*unpack(u2.x) + wv.w*unpack(u3.x));
            o.y = packpair(wv.x*unpack(u0.y) + wv.y*unpack(u1.y) + wv.z*unpack(u2.y) + wv.w*unpack(u3.y));
            o.z = packpair(wv.x*unpack(u0.z) + wv.y*unpack(u1.z) + wv.z*unpack(u2.z) + wv.w*unpack(u3.z));
            o.w = packpair(wv.x*unpack(u0.w) + wv.y*unpack(u1.w) + wv.z*unpack(u2.w) + wv.w*unpack(u3.w));
            int ch = g*2 + q;
            *reinterpret_cast<uint4*>(drow + ((ch ^ sw) << 4)) = o;
        }
    };

    auto compute = [&](int stg) {
        const uint32_t Ab = sbase + stg*DSTG + DA_OFF;
        const uint32_t Bb = sbase + stg*DSTG + DB_OFF;
        #pragma unroll
        for (int s2 = 0; s2 < 4; s2++) {
            uint32_t cxA = (uint32_t)(((s2*2 + (lane >> 4)) ^ l7) << 4);
            uint32_t cxB = (uint32_t)(((s2*2 + ((lane >> 3) & 1)) ^ l7) << 4);
            uint32_t a[4][4], sw4[4][4];
            #pragma unroll
            for (int mf = 0; mf < 4; mf++) {
                ldsm4(a[mf], Ab + (uint32_t)((m0 + mf*16 + aR)*128) + cxA);
                #pragma unroll
                for (int j = 0; j < 4; j++)
                    sw4[mf][j] = prmt(a[mf][j], a[mf][j], 0x1032);
            }
            #pragma unroll
            for (int nb = 0; nb < 2; nb++) {
                uint32_t bb[4];
                ldsm4(bb, Bb + (uint32_t)((n0 + nb*16 + bpx)*128) + cxB);
                #pragma unroll
                for (int mf = 0; mf < 4; mf++) {
                    mma16816(acc[mf*4 + nb*2 + 0], a[mf],   bb[0], bb[1]);
                    mma16816(acc[mf*4 + nb*2 + 1], a[mf],   bb[2], bb[3]);
                    mma16816(acc[mf*4 + nb*2 + 0], sw4[mf], bb[0], bb[1]);
                    mma16816(acc[mf*4 + nb*2 + 1], sw4[mf], bb[2], bb[3]);
                }
            }
        }
    };

    load_chunk(0, 0);
    cpwait0();
    __syncthreads();
    for (int c = 0; c < NCHUNK; c++) {
        int cur = c & 1;
        if (c + 1 < NCHUNK) load_chunk(cur ^ 1, c + 1);
        compute(cur);
        cpwait0();
        __syncthreads();
    }

    // epilogue: out fp32 [oc][NPIX], relu
    const int r  = lane >> 2;
    const int c2 = (lane & 3) * 2;
    #pragma unroll
    for (int mf = 0; mf < 4; mf++) {
        #pragma unroll
        for (int rr = 0; rr < 2; rr++) {
            int oc = m0 + mf*16 + r + rr*8;
            #pragma unroll
            for (int nt = 0; nt < 4; nt++) {
                float* d = acc[mf*4 + nt];
                int x = n0 + nt*8 + c2;
                float2 fv = { fmaxf(d[rr*2], 0.f), fmaxf(d[rr*2+1], 0.f) };
                *reinterpret_cast<float2*>(outf + (size_t)oc*NPIX + pxb + x) = fv;
            }
        }
    }
}

// ---------------- small kernels ----------------
__global__ void __launch_bounds__(256)
conv1x1_27_kernel(const uint32_t* __restrict__ pk, const float* __restrict__ wgt,
                  const float* __restrict__ bias, float* __restrict__ out)
{
    __shared__ float ws[Cn*27];
    for (int idx = threadIdx.x; idx < Cn*27; idx += 256) {
        int o = idx >> 8, ic = idx & 255;
        ws[ic*27 + o] = wgt[(size_t)o*Cn + ic];
    }
    __syncthreads();
    int p  = blockIdx.x * 256 + threadIdx.x;
    int b  = p >> 14;
    int hw = p & (HWn - 1);
    float acc[27];
    #pragma unroll
    for (int o = 0; o < 27; o++) acc[o] = 0.f;
    const uint4* ip = reinterpret_cast<const uint4*>(pk + (size_t)p*256);
    for (int ic4 = 0; ic4 < 64; ic4++) {
        uint4 w = __ldg(ip + ic4);
        float v0 = unpack(w.x), v1 = unpack(w.y), v2 = unpack(w.z), v3 = unpack(w.w);
        const float* w0 = &ws[(ic4*4)*27];
        #pragma unroll
        for (int o = 0; o < 27; o++)
            acc[o] += v0*w0[o] + v1*w0[27+o] + v2*w0[54+o] + v3*w0[81+o];
    }
    #pragma unroll
    for (int o = 0; o < 27; o++)
        out[((size_t)(b*27) + o)*HWn + hw] = acc[o] + bias[o];
}

__global__ void __launch_bounds__(256)
conv1x1_cls_kernel(const float* __restrict__ in, const float* __restrict__ wgt,
                   const float* __restrict__ bias, float* __restrict__ out)
{
    __shared__ float ws[Cn*16];
    int g = blockIdx.y;
    for (int idx = threadIdx.x; idx < Cn*16; idx += 256) {
        int j = idx >> 8, ic = idx & 255;
        ws[ic*16 + j] = wgt[(size_t)(g*16 + j)*Cn + ic];
    }
    __syncthreads();
    int p  = blockIdx.x * 256 + threadIdx.x;
    int b  = p >> 14;
    int hw = p & (HWn - 1);
    float acc[16];
    #pragma unroll
    for (int j = 0; j < 16; j++) acc[j] = 0.f;
    for (int ic = 0; ic < Cn; ic++) {
        float v = __ldg(&in[(size_t)ic*NPIX + p]);
        #pragma unroll
        for (int j = 0; j < 16; j++) acc[j] += v * ws[ic*16 + j];
    }
    #pragma unroll
    for (int j = 0; j < 16; j++) {
        int oc = g*16 + j;
        out[((size_t)(b*NCn) + oc)*HWn + hw] = acc[j] + bias[oc];
    }
}

__global__ void __launch_bounds__(256)
ref_fused_kernel(const float* __restrict__ in, const float* __restrict__ wgt,
                 const float* __restrict__ bias, const float* __restrict__ off,
                 float* __restrict__ dout)
{
    __shared__ float ws[Cn*18];
    for (int idx = threadIdx.x; idx < Cn*18; idx += 256) {
        int o = idx >> 8, ic = idx & 255;
        ws[ic*18 + o] = wgt[(size_t)o*Cn + ic];
    }
    __syncthreads();
    int p  = blockIdx.x * 256 + threadIdx.x;
    int b  = p >> 14;
    int hw = p & (HWn - 1);
    float acc[18];
    #pragma unroll
    for (int o = 0; o < 18; o++) acc[o] = 0.f;
    for (int ic = 0; ic < Cn; ic++) {
        float v = __ldg(&in[(size_t)ic*NPIX + p]);
        #pragma unroll
        for (int o = 0; o < 18; o++) acc[o] += v * ws[ic*18 + o];
    }
    float refine[18];
    #pragma unroll
    for (int o = 0; o < 18; o++)
        refine[o] = acc[o] + bias[o] + off[((size_t)(b*27) + o)*HWn + hw];
    float m0 = 0.f, m1 = 0.f;
    #pragma unroll
    for (int q = 0; q < 9; q++) { m0 += refine[2*q]; m1 += refine[2*q + 1]; }
    m0 *= (1.f/9.f); m1 *= (1.f/9.f);
    float wh0 = 0.f, wh1 = 0.f;
    #pragma unroll
    for (int q = 0; q < 9; q++) {
        wh0 = fmaxf(wh0, fabsf(refine[2*q]     + m0));
        wh1 = fmaxf(wh1, fabsf(refine[2*q + 1] + m1));
    }
    const size_t OUT_WH  = (size_t)Bn*NCn*HWn;
    const size_t OUT_REG = OUT_WH + (size_t)Bn*2*HWn;
    dout[OUT_WH  + ((size_t)(b*2) + 0)*HWn + hw] = wh0;
    dout[OUT_WH  + ((size_t)(b*2) + 1)*HWn + hw] = wh1;
    dout[OUT_REG + ((size_t)(b*2) + 0)*HWn + hw] = m0;
    dout[OUT_REG + ((size_t)(b*2) + 1)*HWn + hw] = m1;
}

// =====================================================================
extern "C" void kernel_launch(void* const* d_in, const int* in_sizes, int n_in,
                              void* d_out, int out_size)
{
    const float* x = (const float*)d_in[0];
    WPtrs wp;
    wp.w[0] = (const float*)d_in[1];   // cls_w0
    wp.w[1] = (const float*)d_in[5];   // cls_w1
    wp.w[2] = (const float*)d_in[9];   // cls_w2
    wp.w[3] = (const float*)d_in[3];   // reg_w0
    wp.w[4] = (const float*)d_in[7];   // reg_w1
    wp.w[5] = (const float*)d_in[11];  // reg_w2
    wp.w[6] = (const float*)d_in[13];  // init_conv_w
    wp.w[7] = (const float*)d_in[17];  // dcn_cls_w
    wp.w[8] = (const float*)d_in[20];  // dcn_ref_w
    const float* cls_b0      = (const float*)d_in[2];
    const float* cls_b1      = (const float*)d_in[6];
    const float* cls_b2      = (const float*)d_in[10];
    const float* reg_b0      = (const float*)d_in[4];
    const float* reg_b1      = (const float*)d_in[8];
    const float* reg_b2      = (const float*)d_in[12];
    const float* init_conv_b = (const float*)d_in[14];
    const float* init_out_w  = (const float*)d_in[15];
    const float* init_out_b  = (const float*)d_in[16];
    const float* cls_out_w   = (const float*)d_in[18];
    const float* cls_out_b   = (const float*)d_in[19];
    const float* ref_out_w   = (const float*)d_in[21];
    const float* ref_out_b   = (const float*)d_in[22];
    float* out = (float*)d_out;

    uint32_t *pkX, *cA, *rA, *cB, *rB, *clspk, *ptspk, *wpk;
    float *off, *dcn0, *dcn1;
    cudaGetSymbolAddress((void**)&pkX,   g_pkX);
    cudaGetSymbolAddress((void**)&cA,    g_cA);
    cudaGetSymbolAddress((void**)&rA,    g_rA);
    cudaGetSymbolAddress((void**)&cB,    g_cB);
    cudaGetSymbolAddress((void**)&rB,    g_rB);
    cudaGetSymbolAddress((void**)&clspk, g_clspk);
    cudaGetSymbolAddress((void**)&ptspk, g_ptspk);
    cudaGetSymbolAddress((void**)&wpk,   g_wpk);
    cudaGetSymbolAddress((void**)&off,   g_off);
    cudaGetSymbolAddress((void**)&dcn0,  g_dcn0);
    cudaGetSymbolAddress((void**)&dcn1,  g_dcn1);

    cudaFuncSetAttribute(conv_kernel, cudaFuncAttributeMaxDynamicSharedMemorySize, CONV_SMEM);
    cudaFuncSetAttribute(dcn_kernel,  cudaFuncAttributeMaxDynamicSharedMemorySize, DCN_SMEM);

    prep_kernel<<<(PKQ + 9*WSZ)/256, 256>>>(x, wp, pkX, wpk);

    auto W = [&](int l) { return (const uint32_t*)(wpk + (size_t)l*WSZ); };

    // dual-conv towers
    {
        ConvJob a{pkX, W(0), cls_b0, cA}, b{pkX, W(3), reg_b0, rA};
        conv_kernel<<<dim3(256,2,2), 256, CONV_SMEM>>>(a, b);
    }
    {
        ConvJob a{cA, W(1), cls_b1, cB}, b{rA, W(4), reg_b1, rB};
        conv_kernel<<<dim3(256,2,2), 256, CONV_SMEM>>>(a, b);
    }
    {
        ConvJob a{cB, W(2), cls_b2, clspk}, b{rB, W(5), reg_b2, ptspk};
        conv_kernel<<<dim3(256,2,2), 256, CONV_SMEM>>>(a, b);
    }
    // init conv (single job)
    {
        ConvJob a{ptspk, W(6), init_conv_b, cA};
        conv_kernel<<<dim3(256,2,1), 256, CONV_SMEM>>>(a, a);
    }
    conv1x1_27_kernel<<<128, 256>>>(cA, init_out_w, init_out_b, off);

    // dual dcn (z=0: cls + mask; z=1: ref no mask)
    dcn_kernel<<<dim3(512,1,2), 256, DCN_SMEM>>>(clspk, ptspk, W(7), W(8), off, dcn0, dcn1);

    conv1x1_cls_kernel<<<dim3(128, 5), 256>>>(dcn0, cls_out_w, cls_out_b, out);
    ref_fused_kernel<<<128, 256>>>(dcn1, ref_out_w, ref_out_b, off, out);
}

// round 11
// speedup vs baseline: 1.2241x; 1.0110x over previous
#include <cuda_runtime.h>
#include <cuda_bf16.h>
#include <math.h>
#include <stdint.h>

#define Cn   256
#define Hn   128
#define Wn   128
#define Bn   2
#define HWn  (Hn*Wn)        // 16384
#define NPIX (Bn*HWn)       // 32768
#define NCn  80
#define Kdcn 2304
#define WSZ  (Cn*Kdcn)      // 589824 words per layer
#define NCHUNK 72
#define NELEM (Bn*Cn*HWn)   // 8388608
#define PKQ  (NELEM/4)

// conv per-stage: A 16KB ([128oc][32w]) + B 16KB ([128px][32w]); XOR swz (ch^row&7)
#define CA_OFF 0
#define CB_OFF 16384
#define CSTG   32768
#define CONV_SMEM (2*CSTG)            // 65536

// dcn per-stage: A 32KB ([256oc][32w]) + B 8KB ([64px][32w])
#define DA_OFF 0
#define DB_OFF 32768
#define DSTG   40960
#define DMETA  (2*DSTG)               // 81920
#define DCN_SMEM (DMETA + 9*64*32)    // 100352

__device__ __forceinline__ uint32_t smem_to_u32(const void* p) {
    uint32_t a;
    asm("{ .reg .u64 t; cvta.to.shared.u64 t, %1; cvt.u32.u64 %0, t; }" : "=r"(a) : "l"(p));
    return a;
}
__device__ __forceinline__ void cpasync16(uint32_t dst, const void* src, uint32_t srcsz) {
    asm volatile("cp.async.cg.shared.global [%0], [%1], 16, %2;"
        :: "r"(dst), "l"(src), "r"(srcsz) : "memory");
}
__device__ __forceinline__ void cpcommit() {
    asm volatile("cp.async.commit_group;" ::: "memory");
}
__device__ __forceinline__ void cpwait0() {
    asm volatile("cp.async.wait_group 0;" ::: "memory");
}
__device__ __forceinline__ void ldsm4(uint32_t r[4], uint32_t addr) {
    asm volatile("ldmatrix.sync.aligned.m8n8.x4.shared.b16 {%0,%1,%2,%3}, [%4];"
        : "=r"(r[0]), "=r"(r[1]), "=r"(r[2]), "=r"(r[3]) : "r"(addr));
}
__device__ __forceinline__ void mma16816(float d[4], const uint32_t a[4],
                                         uint32_t b0, uint32_t b1) {
    asm volatile(
        "mma.sync.aligned.m16n8k16.row.col.f32.bf16.bf16.f32 "
        "{%0,%1,%2,%3}, {%4,%5,%6,%7}, {%8,%9}, {%0,%1,%2,%3};"
        : "+f"(d[0]), "+f"(d[1]), "+f"(d[2]), "+f"(d[3])
        : "r"(a[0]), "r"(a[1]), "r"(a[2]), "r"(a[3]), "r"(b0), "r"(b1));
}
__device__ __forceinline__ uint32_t prmt(uint32_t a, uint32_t b, uint32_t sel) {
    uint32_t d; asm("prmt.b32 %0,%1,%2,%3;" : "=r"(d) : "r"(a), "r"(b), "r"(sel));
    return d;
}
// packed word: low16 = bf16(v), high16 = bf16(v - bf16(v))
__device__ __forceinline__ uint32_t packpair(float v) {
    __nv_bfloat16 h = __float2bfloat16(v);
    float hf = __bfloat162float(h);
    __nv_bfloat16 l = __float2bfloat16(v - hf);
    uint16_t hb = *reinterpret_cast<uint16_t*>(&h);
    uint16_t lb = *reinterpret_cast<uint16_t*>(&l);
    return (uint32_t)hb | ((uint32_t)lb << 16);
}
__device__ __forceinline__ float unpack(uint32_t pk) {
    return __int_as_float(pk << 16) + __int_as_float(pk & 0xFFFF0000u);
}

// ---------------- scratch (channel-last packed activations) ----------------
__device__ uint32_t g_pkX [NELEM];
__device__ uint32_t g_cA  [NELEM];
__device__ uint32_t g_rA  [NELEM];
__device__ uint32_t g_cB  [NELEM];
__device__ uint32_t g_rB  [NELEM];
__device__ uint32_t g_clspk[NELEM];
__device__ uint32_t g_ptspk[NELEM];
__device__ float g_off [Bn*27*HWn];
__device__ float g_dcn0[(size_t)Cn*NPIX];
__device__ float g_dcn1[(size_t)Cn*NPIX];
__device__ __align__(16) uint32_t g_wpk[9*WSZ];

struct WPtrs { const float* w[9]; };

// ---------------- prep: pack x channel-last + split all 9 weights ----------------
__global__ void __launch_bounds__(256)
prep_kernel(const float* __restrict__ x, WPtrs wp,
            uint32_t* __restrict__ pkX, uint32_t* __restrict__ wpk)
{
    int gid = blockIdx.x * 256 + threadIdx.x;
    if (gid < PKQ) {
        int hw  = gid & (HWn - 1);
        int rem = gid >> 14;
        int cg  = rem & 63;
        int b   = rem >> 6;
        const float* src = x + ((size_t)(b*Cn + cg*4))*HWn + hw;
        uint4 o;
        o.x = packpair(__ldg(src));
        o.y = packpair(__ldg(src + HWn));
        o.z = packpair(__ldg(src + 2*HWn));
        o.w = packpair(__ldg(src + 3*HWn));
        *reinterpret_cast<uint4*>(pkX + ((size_t)(b*HWn + hw)*256 + cg*4)) = o;
    } else {
        int i = gid - PKQ;
        int l = i / WSZ, r = i - l*WSZ;
        int oc = r / Kdcn, kp = r - oc*Kdcn;
        int tap = kp >> 8, ic = kp & 255;
        float v = wp.w[l][((size_t)oc*256 + ic)*9 + tap];
        wpk[i] = packpair(v);
    }
}

// =====================================================================
// Dual-job conv3x3 (unchanged from measured-best round 10).
// =====================================================================
struct ConvJob {
    const uint32_t* in;
    const uint32_t* w;
    const float*    bias;
    uint32_t*       outp;
};

__global__ void __launch_bounds__(256, 2)
conv_kernel(ConvJob j0, ConvJob j1)
{
    extern __shared__ __align__(128) char smem[];
    const ConvJob J = blockIdx.z ? j1 : j0;
    const uint32_t sbase = smem_to_u32(smem);
    const int tid  = threadIdx.x;
    const int wid  = tid >> 5, lane = tid & 31;
    const int nblk = blockIdx.x;
    const int b = nblk >> 7, y = nblk & 127;
    const int ocbase = blockIdx.y * 128;

    const int m0 = (wid & 3) * 32;
    const int n0 = (wid >> 2) * 64;
    const int l7  = lane & 7;
    const int aR  = l7 + ((lane >> 3) & 1) * 8;
    const int bpx = l7 + (lane >> 4) * 8;

    float acc[16][4];
    #pragma unroll
    for (int i = 0; i < 16; i++)
        #pragma unroll
        for (int j = 0; j < 4; j++) acc[i][j] = 0.f;

    auto load_chunk = [&](int stg, int cc) {
        const uint32_t su = sbase + stg * CSTG;
        {
            int row = tid >> 1, seg = tid & 1;
            const uint32_t* src = J.w + (size_t)(ocbase + row) * Kdcn + cc * 32;
            uint32_t drow = su + CA_OFF + row * 128;
            int sw = row & 7;
            #pragma unroll
            for (int i = 0; i < 4; i++) {
                int ch = seg*4 + i;
                cpasync16(drow + ((ch ^ sw) << 4), src + ch*4, 16);
            }
        }
        const int tap = cc >> 3;
        const int ic0 = (cc & 7) * 32;
        const int ky = tap / 3 - 1, kx = tap % 3 - 1;
        int p = tid >> 1, seg = tid & 1;
        int yy = y + ky, xx = p + kx;
        bool ok = (yy >= 0 && yy < Hn && xx >= 0 && xx < Wn);
        const uint32_t* src = J.in + ((size_t)(b*HWn + yy*Wn + xx)*256 + ic0);
        uint32_t srcsz = ok ? 16u : 0u;
        uint32_t drow = su + CB_OFF + p * 128;
        int sw = p & 7;
        #pragma unroll
        for (int i = 0; i < 4; i++) {
            int ch = seg*4 + i;
            cpasync16(drow + ((ch ^ sw) << 4), src + ch*4, srcsz);
        }
        cpcommit();
    };

    auto compute = [&](int stg) {
        const uint32_t Ab = sbase + stg*CSTG + CA_OFF;
        const uint32_t Bb = sbase + stg*CSTG + CB_OFF;
        #pragma unroll
        for (int s2 = 0; s2 < 4; s2++) {
            uint32_t cxA = (uint32_t)(((s2*2 + (lane >> 4)) ^ l7) << 4);
            uint32_t cxB = (uint32_t)(((s2*2 + ((lane >> 3) & 1)) ^ l7) << 4);
            uint32_t a0[4], a1[4], s0[4], s1[4];
            ldsm4(a0, Ab + (uint32_t)((m0 + aR)*128)      + cxA);
            ldsm4(a1, Ab + (uint32_t)((m0 + 16 + aR)*128) + cxA);
            #pragma unroll
            for (int j = 0; j < 4; j++) {
                s0[j] = prmt(a0[j], a0[j], 0x1032);
                s1[j] = prmt(a1[j], a1[j], 0x1032);
            }
            #pragma unroll
            for (int nb = 0; nb < 4; nb++) {
                uint32_t bb[4];
                ldsm4(bb, Bb + (uint32_t)((n0 + nb*16 + bpx)*128) + cxB);
                mma16816(acc[nb*2 + 0],     a0, bb[0], bb[1]);
                mma16816(acc[nb*2 + 1],     a0, bb[2], bb[3]);
                mma16816(acc[8 + nb*2 + 0], a1, bb[0], bb[1]);
                mma16816(acc[8 + nb*2 + 1], a1, bb[2], bb[3]);
                mma16816(acc[nb*2 + 0],     s0, bb[0], bb[1]);
                mma16816(acc[nb*2 + 1],     s0, bb[2], bb[3]);
                mma16816(acc[8 + nb*2 + 0], s1, bb[0], bb[1]);
                mma16816(acc[8 + nb*2 + 1], s1, bb[2], bb[3]);
            }
        }
    };

    load_chunk(0, 0);
    cpwait0();
    __syncthreads();
    for (int c = 0; c < NCHUNK; c++) {
        int cur = c & 1;
        if (c + 1 < NCHUNK) load_chunk(cur ^ 1, c + 1);
        compute(cur);
        cpwait0();
        __syncthreads();
    }

    const int r  = lane >> 2;
    const int c2 = (lane & 3) * 2;
    __syncthreads();
    uint32_t* st = reinterpret_cast<uint32_t*>(smem);
    #pragma unroll
    for (int mt = 0; mt < 2; mt++) {
        #pragma unroll
        for (int rr = 0; rr < 2; rr++) {
            int oc_l = m0 + mt*16 + r + rr*8;
            float bv = __ldg(&J.bias[ocbase + oc_l]);
            #pragma unroll
            for (int nt = 0; nt < 8; nt++) {
                float* d = acc[mt*8 + nt];
                int x0 = n0 + nt*8 + c2;
                float v0 = fmaxf(d[rr*2]   + bv, 0.f);
                float v1 = fmaxf(d[rr*2+1] + bv, 0.f);
                st[x0*128     + (oc_l ^ ((x0     & 7) << 2))] = packpair(v0);
                st[(x0+1)*128 + (oc_l ^ (((x0+1) & 7) << 2))] = packpair(v1);
            }
        }
    }
    __syncthreads();
    {
        int p = tid >> 1, half = tid & 1;
        uint32_t* dst = J.outp + ((size_t)(b*HWn + y*Wn + p)*256 + ocbase + half*64);
        int sw = (p & 7) << 2;
        #pragma unroll
        for (int j4 = 0; j4 < 16; j4++) {
            int w = half*64 + j4*4;
            uint4 v = *reinterpret_cast<const uint4*>(st + p*128 + (w ^ sw));
            *reinterpret_cast<uint4*>(dst + j4*4) = v;
        }
    }
}

// =====================================================================
// Dual-job deformable conv with SOFTWARE-PIPELINED gather:
//   gather_ldg(c+1) -> [LDGs in flight] -> compute(c) -> gather_store(c+1)
// D[256oc][64px] per CTA; 256 thr; 2 CTA/SM; grid (512,1,2).
// =====================================================================
__global__ void __launch_bounds__(256, 2)
dcn_kernel(const uint32_t* __restrict__ f0, const uint32_t* __restrict__ f1,
           const uint32_t* __restrict__ w0, const uint32_t* __restrict__ w1,
           const float* __restrict__ off,
           float* __restrict__ o0, float* __restrict__ o1)
{
    extern __shared__ __align__(128) char smem[];
    const int z = blockIdx.z;
    const uint32_t* feat = z ? f1 : f0;
    const uint32_t* wpk  = z ? w1 : w0;
    float* outf          = z ? o1 : o0;
    const bool use_mask  = (z == 0);

    const uint32_t sbase = smem_to_u32(smem);
    const int tid  = threadIdx.x;
    const int wid  = tid >> 5, lane = tid & 31;
    const int pxb  = blockIdx.x * 64;

    const int m0 = (wid & 3) * 64;     // 4 m-warps x 64 oc
    const int n0 = (wid >> 2) * 32;    // 2 n-warps x 32 px
    const int l7  = lane & 7;
    const int aR  = l7 + ((lane >> 3) & 1) * 8;
    const int bpx = l7 + (lane >> 4) * 8;

    // ---- meta: bilinear weights + corner pixel indices per (tap, px) ----
    for (int e = tid; e < 9*64; e += 256) {
        int tap = e >> 6, p = e & 63;
        int pg = pxb + p;
        int b  = pg >> 14;
        int hw = pg & (HWn - 1);
        int y  = hw >> 7, x = hw & 127;
        int ky = tap / 3 - 1, kx = tap % 3 - 1;
        const float* offb = off + (size_t)b*27*HWn + hw;
        float offy = __ldg(offb + (size_t)(2*tap)*HWn);
        float offx = __ldg(offb + (size_t)(2*tap + 1)*HWn);
        float py = (float)(y + ky) + offy;
        float px = (float)(x + kx) + offx;
        float fy0 = floorf(py), fx0 = floorf(px);
        float ly = py - fy0, lx = px - fx0;
        bool vy0 = (fy0 >= 0.f)       && (fy0 <= 127.f);
        bool vy1 = (fy0 + 1.f >= 0.f) && (fy0 + 1.f <= 127.f);
        bool vx0 = (fx0 >= 0.f)       && (fx0 <= 127.f);
        bool vx1 = (fx0 + 1.f >= 0.f) && (fx0 + 1.f <= 127.f);
        float w00 = (1.f-ly)*(1.f-lx) * ((vy0 && vx0) ? 1.f : 0.f);
        float w01 = (1.f-ly)*lx       * ((vy0 && vx1) ? 1.f : 0.f);
        float w10 = ly*(1.f-lx)       * ((vy1 && vx0) ? 1.f : 0.f);
        float w11 = ly*lx             * ((vy1 && vx1) ? 1.f : 0.f);
        if (use_mask) {
            float m = __ldg(offb + (size_t)(18 + tap)*HWn);
            w00 *= m; w01 *= m; w10 *= m; w11 *= m;
        }
        int iy0 = min(max((int)fy0,     0), Hn-1);
        int iy1 = min(max((int)fy0 + 1, 0), Hn-1);
        int ix0 = min(max((int)fx0,     0), Wn-1);
        int ix1 = min(max((int)fx0 + 1, 0), Wn-1);
        char* mb = smem + DMETA + e*32;
        *reinterpret_cast<float4*>(mb) = make_float4(w00, w01, w10, w11);
        *reinterpret_cast<int4*>(mb + 16) =
            make_int4(b*HWn + iy0*Wn + ix0, b*HWn + iy0*Wn + ix1,
                      b*HWn + iy1*Wn + ix0, b*HWn + iy1*Wn + ix1);
    }
    __syncthreads();

    float acc[16][4];
    #pragma unroll
    for (int i = 0; i < 16; i++)
        #pragma unroll
        for (int j = 0; j < 4; j++) acc[i][j] = 0.f;

    const int gp = tid & 63, gg = tid >> 6;   // gather mapping: pixel, 8-word group
    uint4 u[8];                               // gather regs, live across compute

    auto load_a = [&](int stg, int cc) {
        const uint32_t su = sbase + stg * DSTG;
        const uint32_t* src = wpk + (size_t)tid * Kdcn + cc * 32;
        uint32_t drow = su + DA_OFF + tid * 128;
        int sw = tid & 7;
        #pragma unroll
        for (int ch = 0; ch < 8; ch++)
            cpasync16(drow + ((ch ^ sw) << 4), src + ch*4, 16);
        cpcommit();
    };

    auto gather_ldg = [&](int cc) {
        int tap = cc >> 3;
        int ic0 = (cc & 7) * 32;
        const char* mb = smem + DMETA + (tap*64 + gp)*32;
        int4 iv = *reinterpret_cast<const int4*>(mb + 16);
        const uint32_t* c0 = feat + ((size_t)iv.x*256 + ic0 + gg*8);
        const uint32_t* c1 = feat + ((size_t)iv.y*256 + ic0 + gg*8);
        const uint32_t* c2 = feat + ((size_t)iv.z*256 + ic0 + gg*8);
        const uint32_t* c3 = feat + ((size_t)iv.w*256 + ic0 + gg*8);
        u[0] = __ldg((const uint4*)c0); u[1] = __ldg((const uint4*)(c0 + 4));
        u[2] = __ldg((const uint4*)c1); u[3] = __ldg((const uint4*)(c1 + 4));
        u[4] = __ldg((const uint4*)c2); u[5] = __ldg((const uint4*)(c2 + 4));
        u[6] = __ldg((const uint4*)c3); u[7] = __ldg((const uint4*)(c3 + 4));
    };

    auto gather_store = [&](int stg, int cc) {
        int tap = cc >> 3;
        const char* mb = smem + DMETA + (tap*64 + gp)*32;
        float4 wv = *reinterpret_cast<const float4*>(mb);
        char* drow = smem + stg*DSTG + DB_OFF + gp * 128;
        int sw = gp & 7;
        #pragma unroll
        for (int q = 0; q < 2; q++) {
            uint4 u0 = u[q], u1 = u[2+q], u2 = u[4+q], u3 = u[6+q];
            uint4 o;
            o.x = packpair(wv.x*unpack(u0.x) + wv.y*unpack(u1.x) + wv.z*unpack(u2.x) + wv.w*unpack(u3.x));
            o.y = packpair(wv.x*unpack(u0.y) + wv.y*unpack(u1.y) + wv.z*unpack(u2.y) + wv.w*unpack(u3.y));
            o.z = packpair(wv.x*unpack(u0.z) + wv.y*unpack(u1.z) + wv.z*unpack(u2.z) + wv.w*unpack(u3.z));
            o.w = packpair(wv.x*unpack(u0.w) + wv.y*unpack(u1.w) + wv.z*unpack(u2.w) + wv.w*unpack(u3.w));
            int ch = gg*2 + q;
            *reinterpret_cast<uint4*>(drow + ((ch ^ sw) << 4)) = o;
        }
    };

    // compute: B frags held (8 regs), A frags streamed per-mf to bound live regs
    auto compute = [&](int stg) {
        const uint32_t Ab = sbase + stg*DSTG + DA_OFF;
        const uint32_t Bb = sbase + stg*DSTG + DB_OFF;
        #pragma unroll
        for (int s2 = 0; s2 < 4; s2++) {
            uint32_t cxA = (uint32_t)(((s2*2 + (lane >> 4)) ^ l7) << 4);
            uint32_t cxB = (uint32_t)(((s2*2 + ((lane >> 3) & 1)) ^ l7) << 4);
            uint32_t bb0[4], bb1[4];
            ldsm4(bb0, Bb + (uint32_t)((n0 + bpx)*128)      + cxB);
            ldsm4(bb1, Bb + (uint32_t)((n0 + 16 + bpx)*128) + cxB);
            #pragma unroll
            for (int mf = 0; mf < 4; mf++) {
                uint32_t a[4], sw4[4];
                ldsm4(a, Ab + (uint32_t)((m0 + mf*16 + aR)*128) + cxA);
                #pragma unroll
                for (int j = 0; j < 4; j++) sw4[j] = prmt(a[j], a[j], 0x1032);
                mma16816(acc[mf*4 + 0], a,   bb0[0], bb0[1]);
                mma16816(acc[mf*4 + 1], a,   bb0[2], bb0[3]);
                mma16816(acc[mf*4 + 2], a,   bb1[0], bb1[1]);
                mma16816(acc[mf*4 + 3], a,   bb1[2], bb1[3]);
                mma16816(acc[mf*4 + 0], sw4, bb0[0], bb0[1]);
                mma16816(acc[mf*4 + 1], sw4, bb0[2], bb0[3]);
                mma16816(acc[mf*4 + 2], sw4, bb1[0], bb1[1]);
                mma16816(acc[mf*4 + 3], sw4, bb1[2], bb1[3]);
            }
        }
    };

    // prologue: fill stage 0
    load_a(0, 0);
    gather_ldg(0);
    gather_store(0, 0);
    cpwait0();
    __syncthreads();

    for (int c = 0; c < NCHUNK; c++) {
        int cur = c & 1;
        if (c + 1 < NCHUNK) {
            load_a(cur ^ 1, c + 1);
            gather_ldg(c + 1);          // LDGs in flight during compute
        }
        compute(cur);
        if (c + 1 < NCHUNK)
            gather_store(cur ^ 1, c + 1);  // consume landed LDGs
        cpwait0();
        __syncthreads();
    }

    // epilogue: out fp32 [oc][NPIX], relu
    const int r  = lane >> 2;
    const int c2 = (lane & 3) * 2;
    #pragma unroll
    for (int mf = 0; mf < 4; mf++) {
        #pragma unroll
        for (int rr = 0; rr < 2; rr++) {
            int oc = m0 + mf*16 + r + rr*8;
            #pragma unroll
            for (int nt = 0; nt < 2; nt++) {
                // acc layout: [mf*4 + {0,1}] -> bb0 (px n0+0..15), [mf*4 + {2,3}] -> bb1 (px n0+16..31)
                float* dlo = acc[mf*4 + nt*2 + 0];
                float* dhi = acc[mf*4 + nt*2 + 1];
                int x = n0 + nt*16 + c2;
                float2 f0 = { fmaxf(dlo[rr*2], 0.f), fmaxf(dlo[rr*2+1], 0.f) };
                float2 f1 = { fmaxf(dhi[rr*2], 0.f), fmaxf(dhi[rr*2+1], 0.f) };
                *reinterpret_cast<float2*>(outf + (size_t)oc*NPIX + pxb + x)     = f0;
                *reinterpret_cast<float2*>(outf + (size_t)oc*NPIX + pxb + x + 8) = f1;
            }
        }
    }
}

// ---------------- small kernels ----------------
__global__ void __launch_bounds__(256)
conv1x1_27_kernel(const uint32_t* __restrict__ pk, const float* __restrict__ wgt,
                  const float* __restrict__ bias, float* __restrict__ out)
{
    __shared__ float ws[Cn*27];
    for (int idx = threadIdx.x; idx < Cn*27; idx += 256) {
        int o = idx >> 8, ic = idx & 255;
        ws[ic*27 + o] = wgt[(size_t)o*Cn + ic];
    }
    __syncthreads();
    int p  = blockIdx.x * 256 + threadIdx.x;
    int b  = p >> 14;
    int hw = p & (HWn - 1);
    float acc[27];
    #pragma unroll
    for (int o = 0; o < 27; o++) acc[o] = 0.f;
    const uint4* ip = reinterpret_cast<const uint4*>(pk + (size_t)p*256);
    for (int ic4 = 0; ic4 < 64; ic4++) {
        uint4 w = __ldg(ip + ic4);
        float v0 = unpack(w.x), v1 = unpack(w.y), v2 = unpack(w.z), v3 = unpack(w.w);
        const float* w0 = &ws[(ic4*4)*27];
        #pragma unroll
        for (int o = 0; o < 27; o++)
            acc[o] += v0*w0[o] + v1*w0[27+o] + v2*w0[54+o] + v3*w0[81+o];
    }
    #pragma unroll
    for (int o = 0; o < 27; o++)
        out[((size_t)(b*27) + o)*HWn + hw] = acc[o] + bias[o];
}

__global__ void __launch_bounds__(256)
conv1x1_cls_kernel(const float* __restrict__ in, const float* __restrict__ wgt,
                   const float* __restrict__ bias, float* __restrict__ out)
{
    __shared__ float ws[Cn*16];
    int g = blockIdx.y;
    for (int idx = threadIdx.x; idx < Cn*16; idx += 256) {
        int j = idx >> 8, ic = idx & 255;
        ws[ic*16 + j] = wgt[(size_t)(g*16 + j)*Cn + ic];
    }
    __syncthreads();
    int p  = blockIdx.x * 256 + threadIdx.x;
    int b  = p >> 14;
    int hw = p & (HWn - 1);
    float acc[16];
    #pragma unroll
    for (int j = 0; j < 16; j++) acc[j] = 0.f;
    for (int ic = 0; ic < Cn; ic++) {
        float v = __ldg(&in[(size_t)ic*NPIX + p]);
        #pragma unroll
        for (int j = 0; j < 16; j++) acc[j] += v * ws[ic*16 + j];
    }
    #pragma unroll
    for (int j = 0; j < 16; j++) {
        int oc = g*16 + j;
        out[((size_t)(b*NCn) + oc)*HWn + hw] = acc[j] + bias[oc];
    }
}

__global__ void __launch_bounds__(256)
ref_fused_kernel(const float* __restrict__ in, const float* __restrict__ wgt,
                 const float* __restrict__ bias, const float* __restrict__ off,
                 float* __restrict__ dout)
{
    __shared__ float ws[Cn*18];
    for (int idx = threadIdx.x; idx < Cn*18; idx += 256) {
        int o = idx >> 8, ic = idx & 255;
        ws[ic*18 + o] = wgt[(size_t)o*Cn + ic];
    }
    __syncthreads();
    int p  = blockIdx.x * 256 + threadIdx.x;
    int b  = p >> 14;
    int hw = p & (HWn - 1);
    float acc[18];
    #pragma unroll
    for (int o = 0; o < 18; o++) acc[o] = 0.f;
    for (int ic = 0; ic < Cn; ic++) {
        float v = __ldg(&in[(size_t)ic*NPIX + p]);
        #pragma unroll
        for (int o = 0; o < 18; o++) acc[o] += v * ws[ic*18 + o];
    }
    float refine[18];
    #pragma unroll
    for (int o = 0; o < 18; o++)
        refine[o] = acc[o] + bias[o] + off[((size_t)(b*27) + o)*HWn + hw];
    float m0 = 0.f, m1 = 0.f;
    #pragma unroll
    for (int q = 0; q < 9; q++) { m0 += refine[2*q]; m1 += refine[2*q + 1]; }
    m0 *= (1.f/9.f); m1 *= (1.f/9.f);
    float wh0 = 0.f, wh1 = 0.f;
    #pragma unroll
    for (int q = 0; q < 9; q++) {
        wh0 = fmaxf(wh0, fabsf(refine[2*q]     + m0));
        wh1 = fmaxf(wh1, fabsf(refine[2*q + 1] + m1));
    }
    const size_t OUT_WH  = (size_t)Bn*NCn*HWn;
    const size_t OUT_REG = OUT_WH + (size_t)Bn*2*HWn;
    dout[OUT_WH  + ((size_t)(b*2) + 0)*HWn + hw] = wh0;
    dout[OUT_WH  + ((size_t)(b*2) + 1)*HWn + hw] = wh1;
    dout[OUT_REG + ((size_t)(b*2) + 0)*HWn + hw] = m0;
    dout[OUT_REG + ((size_t)(b*2) + 1)*HWn + hw] = m1;
}

// =====================================================================
extern "C" void kernel_launch(void* const* d_in, const int* in_sizes, int n_in,
                              void* d_out, int out_size)
{
    const float* x = (const float*)d_in[0];
    WPtrs wp;
    wp.w[0] = (const float*)d_in[1];   // cls_w0
    wp.w[1] = (const float*)d_in[5];   // cls_w1
    wp.w[2] = (const float*)d_in[9];   // cls_w2
    wp.w[3] = (const float*)d_in[3];   // reg_w0
    wp.w[4] = (const float*)d_in[7];   // reg_w1
    wp.w[5] = (const float*)d_in[11];  // reg_w2
    wp.w[6] = (const float*)d_in[13];  // init_conv_w
    wp.w[7] = (const float*)d_in[17];  // dcn_cls_w
    wp.w[8] = (const float*)d_in[20];  // dcn_ref_w
    const float* cls_b0      = (const float*)d_in[2];
    const float* cls_b1      = (const float*)d_in[6];
    const float* cls_b2      = (const float*)d_in[10];
    const float* reg_b0      = (const float*)d_in[4];
    const float* reg_b1      = (const float*)d_in[8];
    const float* reg_b2      = (const float*)d_in[12];
    const float* init_conv_b = (const float*)d_in[14];
    const float* init_out_w  = (const float*)d_in[15];
    const float* init_out_b  = (const float*)d_in[16];
    const float* cls_out_w   = (const float*)d_in[18];
    const float* cls_out_b   = (const float*)d_in[19];
    const float* ref_out_w   = (const float*)d_in[21];
    const float* ref_out_b   = (const float*)d_in[22];
    float* out = (float*)d_out;

    uint32_t *pkX, *cA, *rA, *cB, *rB, *clspk, *ptspk, *wpk;
    float *off, *dcn0, *dcn1;
    cudaGetSymbolAddress((void**)&pkX,   g_pkX);
    cudaGetSymbolAddress((void**)&cA,    g_cA);
    cudaGetSymbolAddress((void**)&rA,    g_rA);
    cudaGetSymbolAddress((void**)&cB,    g_cB);
    cudaGetSymbolAddress((void**)&rB,    g_rB);
    cudaGetSymbolAddress((void**)&clspk, g_clspk);
    cudaGetSymbolAddress((void**)&ptspk, g_ptspk);
    cudaGetSymbolAddress((void**)&wpk,   g_wpk);
    cudaGetSymbolAddress((void**)&off,   g_off);
    cudaGetSymbolAddress((void**)&dcn0,  g_dcn0);
    cudaGetSymbolAddress((void**)&dcn1,  g_dcn1);

    cudaFuncSetAttribute(conv_kernel, cudaFuncAttributeMaxDynamicSharedMemorySize, CONV_SMEM);
    cudaFuncSetAttribute(dcn_kernel,  cudaFuncAttributeMaxDynamicSharedMemorySize, DCN_SMEM);

    prep_kernel<<<(PKQ + 9*WSZ)/256, 256>>>(x, wp, pkX, wpk);

    auto W = [&](int l) { return (const uint32_t*)(wpk + (size_t)l*WSZ); };

    // dual-conv towers
    {
        ConvJob a{pkX, W(0), cls_b0, cA}, b{pkX, W(3), reg_b0, rA};
        conv_kernel<<<dim3(256,2,2), 256, CONV_SMEM>>>(a, b);
    }
    {
        ConvJob a{cA, W(1), cls_b1, cB}, b{rA, W(4), reg_b1, rB};
        conv_kernel<<<dim3(256,2,2), 256, CONV_SMEM>>>(a, b);
    }
    {
        ConvJob a{cB, W(2), cls_b2, clspk}, b{rB, W(5), reg_b2, ptspk};
        conv_kernel<<<dim3(256,2,2), 256, CONV_SMEM>>>(a, b);
    }
    // init conv (single job)
    {
        ConvJob a{ptspk, W(6), init_conv_b, cA};
        conv_kernel<<<dim3(256,2,1), 256, CONV_SMEM>>>(a, a);
    }
    conv1x1_27_kernel<<<128, 256>>>(cA, init_out_w, init_out_b, off);

    // dual dcn (z=0: cls + mask; z=1: ref no mask), pipelined gather
    dcn_kernel<<<dim3(512,1,2), 256, DCN_SMEM>>>(clspk, ptspk, W(7), W(8), off, dcn0, dcn1);

    conv1x1_cls_kernel<<<dim3(128, 5), 256>>>(dcn0, cls_out_w, cls_out_b, out);
    ref_fused_kernel<<<128, 256>>>(dcn1, ref_out_w, ref_out_b, off, out);
}

// round 12
// speedup vs baseline: 1.2707x; 1.0381x over previous
#include <cuda_runtime.h>
#include <cuda_bf16.h>
#include <math.h>
#include <stdint.h>

#define Cn   256
#define Hn   128
#define Wn   128
#define Bn   2
#define HWn  (Hn*Wn)        // 16384
#define NPIX (Bn*HWn)       // 32768
#define NCn  80
#define Kdcn 2304
#define WSZ  (Cn*Kdcn)      // 589824 weights per layer
#define NCHUNK 72
#define NELEM (Bn*Cn*HWn)   // 8388608
#define PKQ  (NELEM/4)

// conv stage: A hi/lo planes 128oc x 64B, B hi/lo planes 128px x 64B
#define CAH 0
#define CAL 8192
#define CBH 16384
#define CBL 24576
#define CSTG 32768
#define CONV_SMEM (2*CSTG)            // 65536 (epilogue reuses as 64KB staging)

// dcn stage: A hi/lo 256oc x 64B, B hi/lo 64px x 64B
#define DAH 0
#define DAL 16384
#define DBH 32768
#define DBL 36864
#define DSTG 40960
#define DMETA (2*DSTG)                // 81920
#define DCN_SMEM (DMETA + 9*64*32)    // 100352

typedef __nv_bfloat16 bf16;

__device__ __forceinline__ uint32_t smem_to_u32(const void* p) {
    uint32_t a;
    asm("{ .reg .u64 t; cvta.to.shared.u64 t, %1; cvt.u32.u64 %0, t; }" : "=r"(a) : "l"(p));
    return a;
}
__device__ __forceinline__ void cpasync16(uint32_t dst, const void* src, uint32_t srcsz) {
    asm volatile("cp.async.cg.shared.global [%0], [%1], 16, %2;"
        :: "r"(dst), "l"(src), "r"(srcsz) : "memory");
}
__device__ __forceinline__ void cpcommit() {
    asm volatile("cp.async.commit_group;" ::: "memory");
}
__device__ __forceinline__ void cpwait0() {
    asm volatile("cp.async.wait_group 0;" ::: "memory");
}
__device__ __forceinline__ void ldsm4(uint32_t r[4], uint32_t addr) {
    asm volatile("ldmatrix.sync.aligned.m8n8.x4.shared.b16 {%0,%1,%2,%3}, [%4];"
        : "=r"(r[0]), "=r"(r[1]), "=r"(r[2]), "=r"(r[3]) : "r"(addr));
}
__device__ __forceinline__ void mma16816(float d[4], const uint32_t a[4],
                                         uint32_t b0, uint32_t b1) {
    asm volatile(
        "mma.sync.aligned.m16n8k16.row.col.f32.bf16.bf16.f32 "
        "{%0,%1,%2,%3}, {%4,%5,%6,%7}, {%8,%9}, {%0,%1,%2,%3};"
        : "+f"(d[0]), "+f"(d[1]), "+f"(d[2]), "+f"(d[3])
        : "r"(a[0]), "r"(a[1]), "r"(a[2]), "r"(a[3]), "r"(b0), "r"(b1));
}
__device__ __forceinline__ uint32_t prmt(uint32_t a, uint32_t b, uint32_t sel) {
    uint32_t d; asm("prmt.b32 %0,%1,%2,%3;" : "=r"(d) : "r"(a), "r"(b), "r"(sel));
    return d;
}
// packed word: low16 = bf16(v), high16 = bf16(v - bf16(v))
__device__ __forceinline__ uint32_t packpair(float v) {
    bf16 h = __float2bfloat16(v);
    float hf = __bfloat162float(h);
    bf16 l = __float2bfloat16(v - hf);
    uint16_t hb = *reinterpret_cast<uint16_t*>(&h);
    uint16_t lb = *reinterpret_cast<uint16_t*>(&l);
    return (uint32_t)hb | ((uint32_t)lb << 16);
}
__device__ __forceinline__ float bflo(uint32_t w) { return __int_as_float(w << 16); }
__device__ __forceinline__ float bfhi(uint32_t w) { return __int_as_float(w & 0xFFFF0000u); }

// ---------------- scratch: hi/lo bf16 plane maps, channel-last [pix][256] ----------------
__device__ __align__(16) bf16 g_xH [NELEM];
__device__ __align__(16) bf16 g_xL [NELEM];
__device__ __align__(16) bf16 g_aH [NELEM];
__device__ __align__(16) bf16 g_aL [NELEM];
__device__ __align__(16) bf16 g_bH [NELEM];
__device__ __align__(16) bf16 g_bL [NELEM];
__device__ __align__(16) bf16 g_cH [NELEM];
__device__ __align__(16) bf16 g_cL [NELEM];
__device__ __align__(16) bf16 g_dH [NELEM];
__device__ __align__(16) bf16 g_dL [NELEM];
__device__ __align__(16) bf16 g_clsH[NELEM];
__device__ __align__(16) bf16 g_clsL[NELEM];
__device__ __align__(16) bf16 g_ptsH[NELEM];
__device__ __align__(16) bf16 g_ptsL[NELEM];
__device__ float g_off [Bn*27*HWn];
__device__ float g_dcn0[(size_t)Cn*NPIX];
__device__ float g_dcn1[(size_t)Cn*NPIX];
__device__ __align__(16) bf16 g_wH[9*WSZ];
__device__ __align__(16) bf16 g_wL[9*WSZ];

struct WPtrs { const float* w[9]; };

// ---------------- prep: plane-split x + all 9 weights (one launch) ----------------
__global__ void __launch_bounds__(256)
prep_kernel(const float* __restrict__ x, WPtrs wp,
            bf16* __restrict__ xH, bf16* __restrict__ xL,
            bf16* __restrict__ wH, bf16* __restrict__ wL)
{
    int gid = blockIdx.x * 256 + threadIdx.x;
    if (gid < PKQ) {
        int hw  = gid & (HWn - 1);
        int rem = gid >> 14;
        int cg  = rem & 63;
        int b   = rem >> 6;
        const float* src = x + ((size_t)(b*Cn + cg*4))*HWn + hw;
        uint32_t pk0 = packpair(__ldg(src));
        uint32_t pk1 = packpair(__ldg(src + HWn));
        uint32_t pk2 = packpair(__ldg(src + 2*HWn));
        uint32_t pk3 = packpair(__ldg(src + 3*HWn));
        uint2 hv = { prmt(pk0, pk1, 0x5410), prmt(pk2, pk3, 0x5410) };
        uint2 lv = { prmt(pk0, pk1, 0x7632), prmt(pk2, pk3, 0x7632) };
        size_t o = (size_t)(b*HWn + hw)*256 + cg*4;
        *reinterpret_cast<uint2*>(xH + o) = hv;
        *reinterpret_cast<uint2*>(xL + o) = lv;
    } else {
        int i = gid - PKQ;                 // < 9*WSZ
        int l = i / WSZ, r = i - l*WSZ;
        int oc = r / Kdcn, kp = r - oc*Kdcn;
        int tap = kp >> 8, ic = kp & 255;
        float v = wp.w[l][((size_t)oc*256 + ic)*9 + tap];
        bf16 h = __float2bfloat16(v);
        wH[i] = h;
        wL[i] = __float2bfloat16(v - __bfloat162float(h));
    }
}

// =====================================================================
// Dual-job conv3x3, 3-plane MMA (ah*bh + ah*bl + al*bh = 96 MMA/chunk).
// D[128oc][128px] per CTA; 256 thr; 2 CTA/SM; pure cp.async loads.
// =====================================================================
struct ConvJob {
    const bf16* inH; const bf16* inL;
    const bf16* wH;  const bf16* wL;
    const float* bias;
    bf16* outH; bf16* outL;
};

__global__ void __launch_bounds__(256, 2)
conv_kernel(ConvJob j0, ConvJob j1)
{
    extern __shared__ __align__(128) char smem[];
    const ConvJob J = blockIdx.z ? j1 : j0;
    const uint32_t sbase = smem_to_u32(smem);
    const int tid  = threadIdx.x;
    const int wid  = tid >> 5, lane = tid & 31;
    const int nblk = blockIdx.x;
    const int b = nblk >> 7, y = nblk & 127;
    const int ocbase = blockIdx.y * 128;

    const int m0 = (wid & 3) * 32;
    const int n0 = (wid >> 2) * 64;
    const int l7   = lane & 7;
    const int aR   = l7 + ((lane >> 3) & 1) * 8;   // A row-in-16
    const int bpx  = l7 + (lane >> 4) * 8;         // B row-in-16
    const int qA0  = (lane >> 4);                  // A chunk half
    const int qB0  = ((lane >> 3) & 1);            // B chunk half
    const int swzL = (l7 >> 1) & 3;

    float acc[16][4];
    #pragma unroll
    for (int i = 0; i < 16; i++)
        #pragma unroll
        for (int j = 0; j < 4; j++) acc[i][j] = 0.f;

    auto load_chunk = [&](int stg, int cc) {
        const uint32_t su = sbase + stg * CSTG;
        {   // A: 128 oc rows x 64B per plane
            int row = tid >> 1, seg = tid & 1;
            int sw = (row >> 1) & 3;
            const bf16* sH = J.wH + (size_t)(ocbase + row) * Kdcn + cc * 32;
            const bf16* sL = J.wL + (size_t)(ocbase + row) * Kdcn + cc * 32;
            uint32_t drow = su + row * 64;
            #pragma unroll
            for (int i = 0; i < 2; i++) {
                int ch = seg*2 + i;
                uint32_t off = (uint32_t)((ch ^ sw) << 4);
                cpasync16(drow + CAH + off, sH + ch*8, 16);
                cpasync16(drow + CAL + off, sL + ch*8, 16);
            }
        }
        const int tap = cc >> 3;
        const int ic0 = (cc & 7) * 32;
        const int ky = tap / 3 - 1, kx = tap % 3 - 1;
        int p = tid >> 1, seg = tid & 1;
        int yy = y + ky, xx = p + kx;
        bool ok = (yy >= 0 && yy < Hn && xx >= 0 && xx < Wn);
        size_t so = (size_t)(b*HWn + yy*Wn + xx)*256 + ic0;
        uint32_t srcsz = ok ? 16u : 0u;
        int sw = (p >> 1) & 3;
        uint32_t drow = su + p * 64;
        #pragma unroll
        for (int i = 0; i < 2; i++) {
            int ch = seg*2 + i;
            uint32_t off = (uint32_t)((ch ^ sw) << 4);
            cpasync16(drow + CBH + off, J.inH + so + ch*8, srcsz);
            cpasync16(drow + CBL + off, J.inL + so + ch*8, srcsz);
        }
        cpcommit();
    };

    auto compute = [&](int stg) {
        const uint32_t Sb = sbase + stg*CSTG;
        const uint32_t aRow = (uint32_t)((m0 + aR) * 64);
        const uint32_t bRow = (uint32_t)((n0 + bpx) * 64);
        #pragma unroll
        for (int ks = 0; ks < 2; ks++) {
            uint32_t qa = (uint32_t)(((ks*2 + qA0) ^ swzL) << 4);
            uint32_t qb = (uint32_t)(((ks*2 + qB0) ^ swzL) << 4);
            uint32_t ah[2][4], al[2][4];
            ldsm4(ah[0], Sb + CAH + aRow + qa);
            ldsm4(ah[1], Sb + CAH + aRow + 16*64 + qa);
            ldsm4(al[0], Sb + CAL + aRow + qa);
            ldsm4(al[1], Sb + CAL + aRow + 16*64 + qa);
            #pragma unroll
            for (int nb = 0; nb < 4; nb++) {
                uint32_t bh[4], bl[4];
                ldsm4(bh, Sb + CBH + bRow + (uint32_t)(nb*16*64) + qb);
                ldsm4(bl, Sb + CBL + bRow + (uint32_t)(nb*16*64) + qb);
                #pragma unroll
                for (int mt = 0; mt < 2; mt++) {
                    mma16816(acc[mt*8 + 2*nb],     ah[mt], bh[0], bh[1]);
                    mma16816(acc[mt*8 + 2*nb + 1], ah[mt], bh[2], bh[3]);
                    mma16816(acc[mt*8 + 2*nb],     ah[mt], bl[0], bl[1]);
                    mma16816(acc[mt*8 + 2*nb + 1], ah[mt], bl[2], bl[3]);
                    mma16816(acc[mt*8 + 2*nb],     al[mt], bh[0], bh[1]);
                    mma16816(acc[mt*8 + 2*nb + 1], al[mt], bh[2], bh[3]);
                }
            }
        }
    };

    load_chunk(0, 0);
    cpwait0();
    __syncthreads();
    for (int c = 0; c < NCHUNK; c++) {
        int cur = c & 1;
        if (c + 1 < NCHUNK) load_chunk(cur ^ 1, c + 1);
        compute(cur);
        cpwait0();
        __syncthreads();
    }

    // epilogue: stage packed words in smem [px][128 words, swizzled], then split to planes
    const int r  = lane >> 2;
    const int c2 = (lane & 3) * 2;
    __syncthreads();
    uint32_t* st = reinterpret_cast<uint32_t*>(smem);
    #pragma unroll
    for (int mt = 0; mt < 2; mt++) {
        #pragma unroll
        for (int rr = 0; rr < 2; rr++) {
            int oc_l = m0 + mt*16 + r + rr*8;
            float bv = __ldg(&J.bias[ocbase + oc_l]);
            #pragma unroll
            for (int nt = 0; nt < 8; nt++) {
                float* d = acc[mt*8 + nt];
                int x0 = n0 + nt*8 + c2;
                float v0 = fmaxf(d[rr*2]   + bv, 0.f);
                float v1 = fmaxf(d[rr*2+1] + bv, 0.f);
                st[x0*128     + (oc_l ^ ((x0     & 7) << 2))] = packpair(v0);
                st[(x0+1)*128 + (oc_l ^ (((x0+1) & 7) << 2))] = packpair(v1);
            }
        }
    }
    __syncthreads();
    {
        int p = tid >> 1, half = tid & 1;
        int sw = (p & 7) << 2;
        size_t o = (size_t)(b*HWn + y*Wn + p)*256 + ocbase + half*64;
        #pragma unroll
        for (int j4 = 0; j4 < 16; j4++) {
            int w = half*64 + j4*4;
            uint4 v = *reinterpret_cast<const uint4*>(st + p*128 + (w ^ sw));
            uint2 hv = { prmt(v.x, v.y, 0x5410), prmt(v.z, v.w, 0x5410) };
            uint2 lv = { prmt(v.x, v.y, 0x7632), prmt(v.z, v.w, 0x7632) };
            *reinterpret_cast<uint2*>(J.outH + o + j4*4) = hv;
            *reinterpret_cast<uint2*>(J.outL + o + j4*4) = lv;
        }
    }
}

// =====================================================================
// Dual-job deformable conv, 3-plane MMA, pipelined gather.
// D[256oc][64px] per CTA; 256 thr; 2 CTA/SM; grid (512,1,2).
// =====================================================================
__global__ void __launch_bounds__(256, 2)
dcn_kernel(const bf16* __restrict__ f0H, const bf16* __restrict__ f0L,
           const bf16* __restrict__ f1H, const bf16* __restrict__ f1L,
           const bf16* __restrict__ w0H, const bf16* __restrict__ w0L,
           const bf16* __restrict__ w1H, const bf16* __restrict__ w1L,
           const float* __restrict__ off,
           float* __restrict__ o0, float* __restrict__ o1)
{
    extern __shared__ __align__(128) char smem[];
    const int z = blockIdx.z;
    const bf16* featH = z ? f1H : f0H;
    const bf16* featL = z ? f1L : f0L;
    const bf16* wH    = z ? w1H : w0H;
    const bf16* wL    = z ? w1L : w0L;
    float* outf       = z ? o1 : o0;
    const bool use_mask = (z == 0);

    const uint32_t sbase = smem_to_u32(smem);
    const int tid  = threadIdx.x;
    const int wid  = tid >> 5, lane = tid & 31;
    const int pxb  = blockIdx.x * 64;

    const int m0 = (wid & 3) * 64;
    const int n0 = (wid >> 2) * 32;
    const int l7   = lane & 7;
    const int aR   = l7 + ((lane >> 3) & 1) * 8;
    const int bpx  = l7 + (lane >> 4) * 8;
    const int qA0  = (lane >> 4);
    const int qB0  = ((lane >> 3) & 1);
    const int swzL = (l7 >> 1) & 3;

    // ---- meta: bilinear weights + corner pixel indices per (tap, px) ----
    for (int e = tid; e < 9*64; e += 256) {
        int tap = e >> 6, p = e & 63;
        int pg = pxb + p;
        int b  = pg >> 14;
        int hw = pg & (HWn - 1);
        int y  = hw >> 7, x = hw & 127;
        int ky = tap / 3 - 1, kx = tap % 3 - 1;
        const float* offb = off + (size_t)b*27*HWn + hw;
        float offy = __ldg(offb + (size_t)(2*tap)*HWn);
        float offx = __ldg(offb + (size_t)(2*tap + 1)*HWn);
        float py = (float)(y + ky) + offy;
        float px = (float)(x + kx) + offx;
        float fy0 = floorf(py), fx0 = floorf(px);
        float ly = py - fy0, lx = px - fx0;
        bool vy0 = (fy0 >= 0.f)       && (fy0 <= 127.f);
        bool vy1 = (fy0 + 1.f >= 0.f) && (fy0 + 1.f <= 127.f);
        bool vx0 = (fx0 >= 0.f)       && (fx0 <= 127.f);
        bool vx1 = (fx0 + 1.f >= 0.f) && (fx0 + 1.f <= 127.f);
        float w00 = (1.f-ly)*(1.f-lx) * ((vy0 && vx0) ? 1.f : 0.f);
        float w01 = (1.f-ly)*lx       * ((vy0 && vx1) ? 1.f : 0.f);
        float w10 = ly*(1.f-lx)       * ((vy1 && vx0) ? 1.f : 0.f);
        float w11 = ly*lx             * ((vy1 && vx1) ? 1.f : 0.f);
        if (use_mask) {
            float m = __ldg(offb + (size_t)(18 + tap)*HWn);
            w00 *= m; w01 *= m; w10 *= m; w11 *= m;
        }
        int iy0 = min(max((int)fy0,     0), Hn-1);
        int iy1 = min(max((int)fy0 + 1, 0), Hn-1);
        int ix0 = min(max((int)fx0,     0), Wn-1);
        int ix1 = min(max((int)fx0 + 1, 0), Wn-1);
        char* mb = smem + DMETA + e*32;
        *reinterpret_cast<float4*>(mb) = make_float4(w00, w01, w10, w11);
        *reinterpret_cast<int4*>(mb + 16) =
            make_int4(b*HWn + iy0*Wn + ix0, b*HWn + iy0*Wn + ix1,
                      b*HWn + iy1*Wn + ix0, b*HWn + iy1*Wn + ix1);
    }
    __syncthreads();

    float acc[16][4];
    #pragma unroll
    for (int i = 0; i < 16; i++)
        #pragma unroll
        for (int j = 0; j < 4; j++) acc[i][j] = 0.f;

    const int gp = tid & 63, gg = tid >> 6;   // gather: pixel, channel group (8 ch)
    uint4 u[8];                               // 4 H corners + 4 L corners

    auto load_a = [&](int stg, int cc) {
        const uint32_t su = sbase + stg * DSTG;
        const bf16* sH = wH + (size_t)tid * Kdcn + cc * 32;
        const bf16* sL = wL + (size_t)tid * Kdcn + cc * 32;
        uint32_t drow = su + tid * 64;
        int sw = (tid >> 1) & 3;
        #pragma unroll
        for (int ch = 0; ch < 4; ch++) {
            uint32_t o = (uint32_t)((ch ^ sw) << 4);
            cpasync16(drow + DAH + o, sH + ch*8, 16);
            cpasync16(drow + DAL + o, sL + ch*8, 16);
        }
        cpcommit();
    };

    auto gather_ldg = [&](int cc) {
        int tap = cc >> 3;
        int ic0 = (cc & 7) * 32 + gg*8;
        const char* mb = smem + DMETA + (tap*64 + gp)*32;
        int4 iv = *reinterpret_cast<const int4*>(mb + 16);
        u[0] = __ldg((const uint4*)(featH + (size_t)iv.x*256 + ic0));
        u[1] = __ldg((const uint4*)(featH + (size_t)iv.y*256 + ic0));
        u[2] = __ldg((const uint4*)(featH + (size_t)iv.z*256 + ic0));
        u[3] = __ldg((const uint4*)(featH + (size_t)iv.w*256 + ic0));
        u[4] = __ldg((const uint4*)(featL + (size_t)iv.x*256 + ic0));
        u[5] = __ldg((const uint4*)(featL + (size_t)iv.y*256 + ic0));
        u[6] = __ldg((const uint4*)(featL + (size_t)iv.z*256 + ic0));
        u[7] = __ldg((const uint4*)(featL + (size_t)iv.w*256 + ic0));
    };

    auto gather_store = [&](int stg, int cc) {
        int tap = cc >> 3;
        const char* mb = smem + DMETA + (tap*64 + gp)*32;
        float4 wv = *reinterpret_cast<const float4*>(mb);
        uint32_t pk[8];
        #pragma unroll
        for (int j = 0; j < 8; j++) {
            int wi = j >> 1;
            uint32_t h0 = (&u[0].x)[wi], h1 = (&u[1].x)[wi],
                     h2 = (&u[2].x)[wi], h3 = (&u[3].x)[wi];
            uint32_t l0 = (&u[4].x)[wi], l1 = (&u[5].x)[wi],
                     l2 = (&u[6].x)[wi], l3 = (&u[7].x)[wi];
            float v;
            if (j & 1) {
                v = wv.x*(bfhi(h0)+bfhi(l0)) + wv.y*(bfhi(h1)+bfhi(l1))
                  + wv.z*(bfhi(h2)+bfhi(l2)) + wv.w*(bfhi(h3)+bfhi(l3));
            } else {
                v = wv.x*(bflo(h0)+bflo(l0)) + wv.y*(bflo(h1)+bflo(l1))
                  + wv.z*(bflo(h2)+bflo(l2)) + wv.w*(bflo(h3)+bflo(l3));
            }
            pk[j] = packpair(v);
        }
        uint4 hw4 = { prmt(pk[0],pk[1],0x5410), prmt(pk[2],pk[3],0x5410),
                      prmt(pk[4],pk[5],0x5410), prmt(pk[6],pk[7],0x5410) };
        uint4 lw4 = { prmt(pk[0],pk[1],0x7632), prmt(pk[2],pk[3],0x7632),
                      prmt(pk[4],pk[5],0x7632), prmt(pk[6],pk[7],0x7632) };
        int sw = (gp >> 1) & 3;
        uint32_t drow = sbase + stg*DSTG + gp*64 + (uint32_t)((gg ^ sw) << 4);
        *reinterpret_cast<uint4*>(smem + (drow - sbase) + DBH) = hw4;
        *reinterpret_cast<uint4*>(smem + (drow - sbase) + DBL) = lw4;
    };

    auto compute = [&](int stg) {
        const uint32_t Sb = sbase + stg*DSTG;
        const uint32_t bRow = (uint32_t)((n0 + bpx) * 64);
        #pragma unroll
        for (int ks = 0; ks < 2; ks++) {
            uint32_t qa = (uint32_t)(((ks*2 + qA0) ^ swzL) << 4);
            uint32_t qb = (uint32_t)(((ks*2 + qB0) ^ swzL) << 4);
            uint32_t bh0[4], bh1[4], bl0[4], bl1[4];
            ldsm4(bh0, Sb + DBH + bRow + qb);
            ldsm4(bh1, Sb + DBH + bRow + 16*64 + qb);
            ldsm4(bl0, Sb + DBL + bRow + qb);
            ldsm4(bl1, Sb + DBL + bRow + 16*64 + qb);
            #pragma unroll
            for (int mf = 0; mf < 4; mf++) {
                uint32_t aRow = (uint32_t)((m0 + mf*16 + aR) * 64);
                uint32_t ah[4], al[4];
                ldsm4(ah, Sb + DAH + aRow + qa);
                ldsm4(al, Sb + DAL + aRow + qa);
                mma16816(acc[mf*4 + 0], ah, bh0[0], bh0[1]);
                mma16816(acc[mf*4 + 1], ah, bh0[2], bh0[3]);
                mma16816(acc[mf*4 + 2], ah, bh1[0], bh1[1]);
                mma16816(acc[mf*4 + 3], ah, bh1[2], bh1[3]);
                mma16816(acc[mf*4 + 0], ah, bl0[0], bl0[1]);
                mma16816(acc[mf*4 + 1], ah, bl0[2], bl0[3]);
                mma16816(acc[mf*4 + 2], ah, bl1[0], bl1[1]);
                mma16816(acc[mf*4 + 3], ah, bl1[2], bl1[3]);
                mma16816(acc[mf*4 + 0], al, bh0[0], bh0[1]);
                mma16816(acc[mf*4 + 1], al, bh0[2], bh0[3]);
                mma16816(acc[mf*4 + 2], al, bh1[0], bh1[1]);
                mma16816(acc[mf*4 + 3], al, bh1[2], bh1[3]);
            }
        }
    };

    // prologue
    load_a(0, 0);
    gather_ldg(0);
    gather_store(0, 0);
    cpwait0();
    __syncthreads();

    for (int c = 0; c < NCHUNK; c++) {
        int cur = c & 1;
        if (c + 1 < NCHUNK) {
            load_a(cur ^ 1, c + 1);
            gather_ldg(c + 1);
        }
        compute(cur);
        if (c + 1 < NCHUNK)
            gather_store(cur ^ 1, c + 1);
        cpwait0();
        __syncthreads();
    }

    // epilogue: fp32 [oc][NPIX], relu
    const int r  = lane >> 2;
    const int c2 = (lane & 3) * 2;
    #pragma unroll
    for (int mf = 0; mf < 4; mf++) {
        #pragma unroll
        for (int rr = 0; rr < 2; rr++) {
            int oc = m0 + mf*16 + r + rr*8;
            #pragma unroll
            for (int nt = 0; nt < 2; nt++) {
                float* dlo = acc[mf*4 + nt*2 + 0];
                float* dhi = acc[mf*4 + nt*2 + 1];
                int x = n0 + nt*16 + c2;
                float2 f0 = { fmaxf(dlo[rr*2], 0.f), fmaxf(dlo[rr*2+1], 0.f) };
                float2 f1 = { fmaxf(dhi[rr*2], 0.f), fmaxf(dhi[rr*2+1], 0.f) };
                *reinterpret_cast<float2*>(outf + (size_t)oc*NPIX + pxb + x)     = f0;
                *reinterpret_cast<float2*>(outf + (size_t)oc*NPIX + pxb + x + 8) = f1;
            }
        }
    }
}

// ---------------- small kernels ----------------
__global__ void __launch_bounds__(256)
conv1x1_27_kernel(const bf16* __restrict__ inH, const bf16* __restrict__ inL,
                  const float* __restrict__ wgt, const float* __restrict__ bias,
                  float* __restrict__ out)
{
    __shared__ float ws[Cn*27];
    for (int idx = threadIdx.x; idx < Cn*27; idx += 256) {
        int o = idx >> 8, ic = idx & 255;
        ws[ic*27 + o] = wgt[(size_t)o*Cn + ic];
    }
    __syncthreads();
    int p  = blockIdx.x * 256 + threadIdx.x;
    int b  = p >> 14;
    int hw = p & (HWn - 1);
    float acc[27];
    #pragma unroll
    for (int o = 0; o < 27; o++) acc[o] = 0.f;
    const uint4* ipH = reinterpret_cast<const uint4*>(inH + (size_t)p*256);
    const uint4* ipL = reinterpret_cast<const uint4*>(inL + (size_t)p*256);
    for (int g = 0; g < 32; g++) {       // 8 channels per iter
        uint4 h = __ldg(ipH + g), l = __ldg(ipL + g);
        float v[8];
        v[0] = bflo(h.x) + bflo(l.x); v[1] = bfhi(h.x) + bfhi(l.x);
        v[2] = bflo(h.y) + bflo(l.y); v[3] = bfhi(h.y) + bfhi(l.y);
        v[4] = bflo(h.z) + bflo(l.z); v[5] = bfhi(h.z) + bfhi(l.z);
        v[6] = bflo(h.w) + bflo(l.w); v[7] = bfhi(h.w) + bfhi(l.w);
        const float* w0 = &ws[(g*8)*27];
        #pragma unroll
        for (int j = 0; j < 8; j++)
            #pragma unroll
            for (int o = 0; o < 27; o++)
                acc[o] += v[j] * w0[j*27 + o];
    }
    #pragma unroll
    for (int o = 0; o < 27; o++)
        out[((size_t)(b*27) + o)*HWn + hw] = acc[o] + bias[o];
}

__global__ void __launch_bounds__(256)
conv1x1_cls_kernel(const float* __restrict__ in, const float* __restrict__ wgt,
                   const float* __restrict__ bias, float* __restrict__ out)
{
    __shared__ float ws[Cn*16];
    int g = blockIdx.y;
    for (int idx = threadIdx.x; idx < Cn*16; idx += 256) {
        int j = idx >> 8, ic = idx & 255;
        ws[ic*16 + j] = wgt[(size_t)(g*16 + j)*Cn + ic];
    }
    __syncthreads();
    int p  = blockIdx.x * 256 + threadIdx.x;
    int b  = p >> 14;
    int hw = p & (HWn - 1);
    float acc[16];
    #pragma unroll
    for (int j = 0; j < 16; j++) acc[j] = 0.f;
    for (int ic = 0; ic < Cn; ic++) {
        float v = __ldg(&in[(size_t)ic*NPIX + p]);
        #pragma unroll
        for (int j = 0; j < 16; j++) acc[j] += v * ws[ic*16 + j];
    }
    #pragma unroll
    for (int j = 0; j < 16; j++) {
        int oc = g*16 + j;
        out[((size_t)(b*NCn) + oc)*HWn + hw] = acc[j] + bias[oc];
    }
}

__global__ void __launch_bounds__(256)
ref_fused_kernel(const float* __restrict__ in, const float* __restrict__ wgt,
                 const float* __restrict__ bias, const float* __restrict__ off,
                 float* __restrict__ dout)
{
    __shared__ float ws[Cn*18];
    for (int idx = threadIdx.x; idx < Cn*18; idx += 256) {
        int o = idx >> 8, ic = idx & 255;
        ws[ic*18 + o] = wgt[(size_t)o*Cn + ic];
    }
    __syncthreads();
    int p  = blockIdx.x * 256 + threadIdx.x;
    int b  = p >> 14;
    int hw = p & (HWn - 1);
    float acc[18];
    #pragma unroll
    for (int o = 0; o < 18; o++) acc[o] = 0.f;
    for (int ic = 0; ic < Cn; ic++) {
        float v = __ldg(&in[(size_t)ic*NPIX + p]);
        #pragma unroll
        for (int o = 0; o < 18; o++) acc[o] += v * ws[ic*18 + o];
    }
    float refine[18];
    #pragma unroll
    for (int o = 0; o < 18; o++)
        refine[o] = acc[o] + bias[o] + off[((size_t)(b*27) + o)*HWn + hw];
    float m0 = 0.f, m1 = 0.f;
    #pragma unroll
    for (int q = 0; q < 9; q++) { m0 += refine[2*q]; m1 += refine[2*q + 1]; }
    m0 *= (1.f/9.f); m1 *= (1.f/9.f);
    float wh0 = 0.f, wh1 = 0.f;
    #pragma unroll
    for (int q = 0; q < 9; q++) {
        wh0 = fmaxf(wh0, fabsf(refine[2*q]     + m0));
        wh1 = fmaxf(wh1, fabsf(refine[2*q + 1] + m1));
    }
    const size_t OUT_WH  = (size_t)Bn*NCn*HWn;
    const size_t OUT_REG = OUT_WH + (size_t)Bn*2*HWn;
    dout[OUT_WH  + ((size_t)(b*2) + 0)*HWn + hw] = wh0;
    dout[OUT_WH  + ((size_t)(b*2) + 1)*HWn + hw] = wh1;
    dout[OUT_REG + ((size_t)(b*2) + 0)*HWn + hw] = m0;
    dout[OUT_REG + ((size_t)(b*2) + 1)*HWn + hw] = m1;
}

// =====================================================================
extern "C" void kernel_launch(void* const* d_in, const int* in_sizes, int n_in,
                              void* d_out, int out_size)
{
    const float* x = (const float*)d_in[0];
    WPtrs wp;
    wp.w[0] = (const float*)d_in[1];   // cls_w0
    wp.w[1] = (const float*)d_in[5];   // cls_w1
    wp.w[2] = (const float*)d_in[9];   // cls_w2
    wp.w[3] = (const float*)d_in[3];   // reg_w0
    wp.w[4] = (const float*)d_in[7];   // reg_w1
    wp.w[5] = (const float*)d_in[11];  // reg_w2
    wp.w[6] = (const float*)d_in[13];  // init_conv_w
    wp.w[7] = (const float*)d_in[17];  // dcn_cls_w
    wp.w[8] = (const float*)d_in[20];  // dcn_ref_w
    const float* cls_b0      = (const float*)d_in[2];
    const float* cls_b1      = (const float*)d_in[6];
    const float* cls_b2      = (const float*)d_in[10];
    const float* reg_b0      = (const float*)d_in[4];
    const float* reg_b1      = (const float*)d_in[8];
    const float* reg_b2      = (const float*)d_in[12];
    const float* init_conv_b = (const float*)d_in[14];
    const float* init_out_w  = (const float*)d_in[15];
    const float* init_out_b  = (const float*)d_in[16];
    const float* cls_out_w   = (const float*)d_in[18];
    const float* cls_out_b   = (const float*)d_in[19];
    const float* ref_out_w   = (const float*)d_in[21];
    const float* ref_out_b   = (const float*)d_in[22];
    float* out = (float*)d_out;

    bf16 *xH,*xL,*aH,*aL,*bH,*bL,*cH,*cL,*dH,*dL,*clsH,*clsL,*ptsH,*ptsL,*wH,*wL;
    float *off, *dcn0, *dcn1;
    cudaGetSymbolAddress((void**)&xH,  g_xH);   cudaGetSymbolAddress((void**)&xL,  g_xL);
    cudaGetSymbolAddress((void**)&aH,  g_aH);   cudaGetSymbolAddress((void**)&aL,  g_aL);
    cudaGetSymbolAddress((void**)&bH,  g_bH);   cudaGetSymbolAddress((void**)&bL,  g_bL);
    cudaGetSymbolAddress((void**)&cH,  g_cH);   cudaGetSymbolAddress((void**)&cL,  g_cL);
    cudaGetSymbolAddress((void**)&dH,  g_dH);   cudaGetSymbolAddress((void**)&dL,  g_dL);
    cudaGetSymbolAddress((void**)&clsH, g_clsH); cudaGetSymbolAddress((void**)&clsL, g_clsL);
    cudaGetSymbolAddress((void**)&ptsH, g_ptsH); cudaGetSymbolAddress((void**)&ptsL, g_ptsL);
    cudaGetSymbolAddress((void**)&wH,  g_wH);   cudaGetSymbolAddress((void**)&wL,  g_wL);
    cudaGetSymbolAddress((void**)&off, g_off);
    cudaGetSymbolAddress((void**)&dcn0, g_dcn0);
    cudaGetSymbolAddress((void**)&dcn1, g_dcn1);

    cudaFuncSetAttribute(conv_kernel, cudaFuncAttributeMaxDynamicSharedMemorySize, CONV_SMEM);
    cudaFuncSetAttribute(dcn_kernel,  cudaFuncAttributeMaxDynamicSharedMemorySize, DCN_SMEM);

    prep_kernel<<<(PKQ + 9*WSZ)/256, 256>>>(x, wp, xH, xL, wH, wL);

    auto WH = [&](int l) { return (const bf16*)(wH + (size_t)l*WSZ); };
    auto WL = [&](int l) { return (const bf16*)(wL + (size_t)l*WSZ); };

    // dual-conv towers
    {
        ConvJob a{xH, xL, WH(0), WL(0), cls_b0, aH, aL};
        ConvJob b{xH, xL, WH(3), WL(3), reg_b0, cH, cL};
        conv_kernel<<<dim3(256,2,2), 256, CONV_SMEM>>>(a, b);
    }
    {
        ConvJob a{aH, aL, WH(1), WL(1), cls_b1, bH, bL};
        ConvJob b{cH, cL, WH(4), WL(4), reg_b1, dH, dL};
        conv_kernel<<<dim3(256,2,2), 256, CONV_SMEM>>>(a, b);
    }
    {
        ConvJob a{bH, bL, WH(2), WL(2), cls_b2, clsH, clsL};
        ConvJob b{dH, dL, WH(5), WL(5), reg_b2, ptsH, ptsL};
        conv_kernel<<<dim3(256,2,2), 256, CONV_SMEM>>>(a, b);
    }
    // init conv (single job)
    {
        ConvJob a{ptsH, ptsL, WH(6), WL(6), init_conv_b, aH, aL};
        conv_kernel<<<dim3(256,2,1), 256, CONV_SMEM>>>(a, a);
    }
    conv1x1_27_kernel<<<128, 256>>>(aH, aL, init_out_w, init_out_b, off);

    // dual dcn (z=0: cls + mask; z=1: ref no mask)
    dcn_kernel<<<dim3(512,1,2), 256, DCN_SMEM>>>(clsH, clsL, ptsH, ptsL,
                                                 WH(7), WL(7), WH(8), WL(8),
                                                 off, dcn0, dcn1);

    conv1x1_cls_kernel<<<dim3(128, 5), 256>>>(dcn0, cls_out_w, cls_out_b, out);
    ref_fused_kernel<<<128, 256>>>(dcn1, ref_out_w, ref_out_b, off, out);
}